// round 3
// baseline (speedup 1.0000x reference)
#include <cuda_runtime.h>
#include <math.h>

#define NMAX 100000
#define EMAX 1600000
#define NEG_SLOPE 0.2f
#define LN_EPS 1e-5f

// ---------------- scratch (device globals; no allocation) ----------------
__device__ float g_h[NMAX * 64];         // per-layer linear output (reused)
__device__ float g_x1[NMAX * 64];        // layer-1 output (input to layer 2)
__device__ float g_s[NMAX * 4];          // per-node src attention logits
__device__ float g_d[NMAX * 4];          // per-node dst attention logits
__device__ int   g_deg[NMAX];            // in-degree histogram
__device__ int   g_rowptr[NMAX + 1];     // CSR row pointers (by dst)
__device__ int   g_wptr[NMAX];           // scatter cursors
__device__ int   g_csrc[EMAX];           // CSR src ids
__device__ float g_gacc[64];             // column sums for global mean

__device__ __forceinline__ float lrelu(float v) {
    return v > 0.0f ? v : NEG_SLOPE * v;
}

// ---------------- small fills ----------------
__global__ void fillf(float* p, float v, int n) {
    int i = blockIdx.x * blockDim.x + threadIdx.x;
    if (i < n) p[i] = v;
}
__global__ void filli(int* p, int v, int n) {
    int i = blockIdx.x * blockDim.x + threadIdx.x;
    if (i < n) p[i] = v;
}

// ---------------- CSR build ----------------
__global__ void hist_deg(const int* __restrict__ ei, int E, int* __restrict__ deg) {
    int e = blockIdx.x * blockDim.x + threadIdx.x;
    if (e < E) atomicAdd(&deg[ei[E + e]], 1);
}

// single-block exclusive scan of deg -> rowptr (+copy to wptr)
__global__ void scan_deg(const int* __restrict__ deg, int n,
                         int* __restrict__ rowptr, int* __restrict__ wptr) {
    __shared__ int part[1024];
    int t = threadIdx.x;
    int chunk = (n + 1023) / 1024;
    int beg = t * chunk;
    int end = beg + chunk < n ? beg + chunk : n;
    int s = 0;
    for (int i = beg; i < end; i++) s += deg[i];
    part[t] = s;
    __syncthreads();
    // Hillis-Steele inclusive scan
    for (int off = 1; off < 1024; off <<= 1) {
        int add = (t >= off) ? part[t - off] : 0;
        __syncthreads();
        part[t] += add;
        __syncthreads();
    }
    int run = part[t] - s;          // exclusive prefix for this chunk
    for (int i = beg; i < end; i++) {
        rowptr[i] = run;
        wptr[i] = run;
        run += deg[i];
    }
    if (t == 1023) rowptr[n] = part[1023];
}

__global__ void scatter_csr(const int* __restrict__ ei, int E,
                            int* __restrict__ wptr, int* __restrict__ csrc) {
    int e = blockIdx.x * blockDim.x + threadIdx.x;
    if (e >= E) return;
    int d = ei[E + e];
    int pos = atomicAdd(&wptr[d], 1);
    csrc[pos] = ei[e];
}

// ---------------- fused linear + attention logits ----------------
// block = 256 threads = 4 nodes x 64 output cols. W staged in smem.
// TEMP=1: layer-1 variant, builds concat(x, relu(tf*Wt+bt)) on the fly.
template <int TEMP>
__global__ void lin_att(const float* __restrict__ in, int in_dim,
                        const float* __restrict__ tf, const float* __restrict__ Wt,
                        const float* __restrict__ bt,
                        const float* __restrict__ W,
                        const float* __restrict__ a_src, const float* __restrict__ a_dst,
                        float* __restrict__ h_out, float* __restrict__ s_out,
                        float* __restrict__ d_out_, int n) {
    __shared__ float sW[72 * 64];
    __shared__ float sx[4 * 72];
    __shared__ float sas[64], sad[64];
    __shared__ float sWt[16], sbt[16];
    int tid = threadIdx.x;
    for (int i = tid; i < in_dim * 64; i += 256) sW[i] = W[i];
    if (tid < 64) { sas[tid] = a_src[tid]; sad[tid] = a_dst[tid]; }
    if (TEMP && tid < 16) { sWt[tid] = Wt[tid]; sbt[tid] = bt[tid]; }
    __syncthreads();

    int lane = tid & 31;
    int node_local = tid >> 6;   // 0..3
    int j = tid & 63;            // output column

    for (int g0 = blockIdx.x * 4; g0 < n; g0 += gridDim.x * 4) {
        __syncthreads();
        for (int i = tid; i < 4 * in_dim; i += 256) {
            int nl = i / in_dim, c = i % in_dim;
            int node = g0 + nl;
            float v = 0.0f;
            if (node < n) {
                if (TEMP) {
                    if (c < 56) v = in[(long)node * 56 + c];
                    else {
                        float t = tf[node] * sWt[c - 56] + sbt[c - 56];
                        v = t > 0.0f ? t : 0.0f;
                    }
                } else {
                    v = in[(long)node * 64 + c];
                }
            }
            sx[nl * in_dim + c] = v;
        }
        __syncthreads();
        int node = g0 + node_local;
        if (node < n) {
            const float* xr = &sx[node_local * in_dim];
            float acc = 0.0f;
#pragma unroll 8
            for (int k = 0; k < in_dim; k++) acc = fmaf(xr[k], sW[k * 64 + j], acc);
            h_out[(long)node * 64 + j] = acc;
            float ps = acc * sas[j];
            float pd = acc * sad[j];
#pragma unroll
            for (int off = 8; off; off >>= 1) {
                ps += __shfl_down_sync(0xffffffffu, ps, off, 16);
                pd += __shfl_down_sync(0xffffffffu, pd, off, 16);
            }
            if ((lane & 15) == 0) {
                int head = j >> 4;
                s_out[node * 4 + head] = ps;
                d_out_[node * 4 + head] = pd;
            }
        }
    }
}

// ---------------- fused GAT aggregation + softmax-normalize + LN + ReLU ----------------
// half-warp (16 lanes) per dst node; lane owns 4 consecutive output columns.
// Self-loop handled analytically (not in CSR).
__global__ void gat_agg(const int* __restrict__ rowptr, const int* __restrict__ csrc,
                        const float* __restrict__ s_, const float* __restrict__ d_,
                        const float* __restrict__ h_,
                        const float* __restrict__ b,
                        const float* __restrict__ gma, const float* __restrict__ bta,
                        float* __restrict__ out, int n) {
    int l = threadIdx.x & 15;
    int node = blockIdx.x * (blockDim.x >> 4) + (threadIdx.x >> 4);
    if (node >= n) return;
    int head = l >> 2;
    float dlog = d_[node * 4 + head];

    // self-loop
    float w = __expf(lrelu(s_[node * 4 + head] + dlog));
    float z = w;
    float4 hv = *(const float4*)&h_[(long)node * 64 + l * 4];
    float4 acc = make_float4(w * hv.x, w * hv.y, w * hv.z, w * hv.w);

    int beg = rowptr[node], end = rowptr[node + 1];
    for (int i = beg; i < end; i++) {
        int src = csrc[i];                       // broadcast load
        w = __expf(lrelu(s_[src * 4 + head] + dlog));
        z += w;
        hv = *(const float4*)&h_[(long)src * 64 + l * 4];
        acc.x = fmaf(w, hv.x, acc.x);
        acc.y = fmaf(w, hv.y, acc.y);
        acc.z = fmaf(w, hv.z, acc.z);
        acc.w = fmaf(w, hv.w, acc.w);
    }
    float zinv = 1.0f / (z + 1e-16f);
    float4 v;
    v.x = acc.x * zinv + b[l * 4 + 0];
    v.y = acc.y * zinv + b[l * 4 + 1];
    v.z = acc.z * zinv + b[l * 4 + 2];
    v.w = acc.w * zinv + b[l * 4 + 3];

    // LayerNorm over the 64 values held by this half-warp
    float sum = v.x + v.y + v.z + v.w;
    float sq  = v.x * v.x + v.y * v.y + v.z * v.z + v.w * v.w;
#pragma unroll
    for (int off = 8; off; off >>= 1) {
        sum += __shfl_xor_sync(0xffffffffu, sum, off, 16);
        sq  += __shfl_xor_sync(0xffffffffu, sq, off, 16);
    }
    float mean = sum * (1.0f / 64.0f);
    float var  = sq * (1.0f / 64.0f) - mean * mean;
    float inv  = rsqrtf(var + LN_EPS);
    float4 o;
    o.x = (v.x - mean) * inv * gma[l * 4 + 0] + bta[l * 4 + 0];
    o.y = (v.y - mean) * inv * gma[l * 4 + 1] + bta[l * 4 + 1];
    o.z = (v.z - mean) * inv * gma[l * 4 + 2] + bta[l * 4 + 2];
    o.w = (v.w - mean) * inv * gma[l * 4 + 3] + bta[l * 4 + 3];
    o.x = o.x > 0.0f ? o.x : 0.0f;
    o.y = o.y > 0.0f ? o.y : 0.0f;
    o.z = o.z > 0.0f ? o.z : 0.0f;
    o.w = o.w > 0.0f ? o.w : 0.0f;
    *(float4*)&out[(long)node * 64 + l * 4] = o;
}

// ---------------- global mean (column sums) ----------------
__global__ void colsum(const float* __restrict__ x2, int n, float* __restrict__ acc) {
    int col = threadIdx.x & 63;
    int rowgrp = threadIdx.x >> 6;  // 0..3
    float s = 0.0f;
    for (int r = blockIdx.x * 4 + rowgrp; r < n; r += gridDim.x * 4)
        s += x2[(long)r * 64 + col];
    __shared__ float sm[256];
    sm[threadIdx.x] = s;
    __syncthreads();
    if (threadIdx.x < 64) {
        float t = sm[threadIdx.x] + sm[threadIdx.x + 64] +
                  sm[threadIdx.x + 128] + sm[threadIdx.x + 192];
        atomicAdd(&acc[threadIdx.x], t);
    }
}

// ---------------- final MLP on mean-pooled embedding ----------------
__global__ void final_mlp(const float* __restrict__ acc, int n,
                          const float* __restrict__ Wp1, const float* __restrict__ bp1,
                          const float* __restrict__ Wp2, const float* __restrict__ bp2,
                          float* __restrict__ out) {
    __shared__ float gein[64], hid[64];
    int t = threadIdx.x;  // 64 threads
    gein[t] = acc[t] / (float)n;
    __syncthreads();
    float a = bp1[t];
#pragma unroll
    for (int k = 0; k < 64; k++) a = fmaf(gein[k], Wp1[k * 64 + t], a);
    hid[t] = a > 0.0f ? a : 0.0f;
    __syncthreads();
    float o = bp2[t];
#pragma unroll
    for (int k = 0; k < 64; k++) o = fmaf(hid[k], Wp2[k * 64 + t], o);
    out[t] = o;
}

// ---------------- host launch ----------------
extern "C" void kernel_launch(void* const* d_in, const int* in_sizes, int n_in,
                              void* d_out, int out_size) {
    const float* x   = (const float*)d_in[0];
    const float* tf  = (const float*)d_in[1];
    const int*   ei  = (const int*)d_in[2];
    const float* Wt  = (const float*)d_in[3];
    const float* bt  = (const float*)d_in[4];
    const float* W1  = (const float*)d_in[5];
    const float* as1 = (const float*)d_in[6];
    const float* ad1 = (const float*)d_in[7];
    const float* b1  = (const float*)d_in[8];
    const float* g1  = (const float*)d_in[9];
    const float* be1 = (const float*)d_in[10];
    const float* W2  = (const float*)d_in[11];
    const float* as2 = (const float*)d_in[12];
    const float* ad2 = (const float*)d_in[13];
    const float* b2  = (const float*)d_in[14];
    const float* g2  = (const float*)d_in[15];
    const float* be2 = (const float*)d_in[16];
    const float* Wp1 = (const float*)d_in[17];
    const float* bp1 = (const float*)d_in[18];
    const float* Wp2 = (const float*)d_in[19];
    const float* bp2 = (const float*)d_in[20];

    int n = in_sizes[0] / 56;
    int E = in_sizes[2] / 2;

    float* out = (float*)d_out;
    float* x2  = out;              // [n, 64]
    float* ge  = out + (long)n * 64;

    float *h, *x1, *s, *d, *gacc;
    int *deg, *rowptr, *wptr, *csrc;
    cudaGetSymbolAddress((void**)&h,      g_h);
    cudaGetSymbolAddress((void**)&x1,     g_x1);
    cudaGetSymbolAddress((void**)&s,      g_s);
    cudaGetSymbolAddress((void**)&d,      g_d);
    cudaGetSymbolAddress((void**)&gacc,   g_gacc);
    cudaGetSymbolAddress((void**)&deg,    g_deg);
    cudaGetSymbolAddress((void**)&rowptr, g_rowptr);
    cudaGetSymbolAddress((void**)&wptr,   g_wptr);
    cudaGetSymbolAddress((void**)&csrc,   g_csrc);

    const int TB = 256;
    int ebk = (E + TB - 1) / TB;
    int nhb = (n + 15) / 16;     // half-warp-per-node blocks (16 nodes/block)

    // ---- CSR build (shared by both layers) ----
    filli<<<(n + TB - 1) / TB, TB>>>(deg, 0, n);
    hist_deg<<<ebk, TB>>>(ei, E, deg);
    scan_deg<<<1, 1024>>>(deg, n, rowptr, wptr);
    scatter_csr<<<ebk, TB>>>(ei, E, wptr, csrc);

    // ---- layer 1 (temporal concat fused into lin_att) ----
    lin_att<1><<<2048, TB>>>(x, 72, tf, Wt, bt, W1, as1, ad1, h, s, d, n);
    gat_agg<<<nhb, TB>>>(rowptr, csrc, s, d, h, b1, g1, be1, x1, n);

    // ---- layer 2 ----
    lin_att<0><<<2048, TB>>>(x1, 64, tf, Wt, bt, W2, as2, ad2, h, s, d, n);
    gat_agg<<<nhb, TB>>>(rowptr, csrc, s, d, h, b2, g2, be2, x2, n);

    // ---- global mean pool + MLP ----
    fillf<<<1, 64>>>(gacc, 0.0f, 64);
    colsum<<<1024, TB>>>(x2, n, gacc);
    final_mlp<<<1, 64>>>(gacc, n, Wp1, bp1, Wp2, bp2, ge);
}

// round 4
// speedup vs baseline: 1.0718x; 1.0718x over previous
#include <cuda_runtime.h>
#include <math.h>

#define NMAX 100000
#define EMAX 1600000
#define NEG_SLOPE 0.2f
#define LN_EPS 1e-5f

// ---------------- scratch (device globals; no allocation) ----------------
__device__ float g_h[NMAX * 64];         // per-layer linear output (reused)
__device__ float g_x1[NMAX * 64];        // layer-1 output (input to layer 2)
__device__ float g_s[NMAX * 4];          // per-node src attention logits
__device__ float g_d[NMAX * 4];          // per-node dst attention logits
__device__ int   g_deg[NMAX];            // in-degree histogram
__device__ int   g_rowptr[NMAX + 1];     // CSR row pointers (by dst)
__device__ int   g_wptr[NMAX];           // scatter cursors
__device__ int   g_csrc[EMAX];           // CSR src ids
__device__ float g_gacc[64];             // column sums for global mean

__device__ __forceinline__ float lrelu(float v) {
    return v > 0.0f ? v : NEG_SLOPE * v;
}

// ---------------- small fills ----------------
__global__ void fillf(float* p, float v, int n) {
    int i = blockIdx.x * blockDim.x + threadIdx.x;
    if (i < n) p[i] = v;
}
__global__ void filli(int* p, int v, int n) {
    int i = blockIdx.x * blockDim.x + threadIdx.x;
    if (i < n) p[i] = v;
}

// ---------------- CSR build ----------------
__global__ void hist_deg(const int* __restrict__ ei, int E, int* __restrict__ deg) {
    int e = blockIdx.x * blockDim.x + threadIdx.x;
    if (e < E) atomicAdd(&deg[ei[E + e]], 1);
}

// single-block exclusive scan of deg -> rowptr (+copy to wptr)
__global__ void scan_deg(const int* __restrict__ deg, int n,
                         int* __restrict__ rowptr, int* __restrict__ wptr) {
    __shared__ int part[1024];
    int t = threadIdx.x;
    int chunk = (n + 1023) / 1024;
    int beg = t * chunk;
    int end = beg + chunk < n ? beg + chunk : n;
    int s = 0;
    for (int i = beg; i < end; i++) s += deg[i];
    part[t] = s;
    __syncthreads();
    for (int off = 1; off < 1024; off <<= 1) {
        int add = (t >= off) ? part[t - off] : 0;
        __syncthreads();
        part[t] += add;
        __syncthreads();
    }
    int run = part[t] - s;          // exclusive prefix for this chunk
    for (int i = beg; i < end; i++) {
        rowptr[i] = run;
        wptr[i] = run;
        run += deg[i];
    }
    if (t == 1023) rowptr[n] = part[1023];
}

__global__ void scatter_csr(const int* __restrict__ ei, int E,
                            int* __restrict__ wptr, int* __restrict__ csrc) {
    int e = blockIdx.x * blockDim.x + threadIdx.x;
    if (e >= E) return;
    int d = ei[E + e];
    int pos = atomicAdd(&wptr[d], 1);
    csrc[pos] = ei[e];
}

// ---------------- fused linear + attention logits ----------------
// block = 256 threads = 4 nodes x 64 output cols.
// W transposed into smem [64][76] so each thread streams its column via LDS.128.
// x rows read via float4 broadcast. TEMP=1 fuses the temporal encoder.
template <int TEMP, int IN_DIM>
__global__ void lin_att(const float* __restrict__ in,
                        const float* __restrict__ tf, const float* __restrict__ Wt,
                        const float* __restrict__ bt,
                        const float* __restrict__ W,
                        const float* __restrict__ a_src, const float* __restrict__ a_dst,
                        float* __restrict__ h_out, float* __restrict__ s_out,
                        float* __restrict__ d_out_, int n) {
    __shared__ float sWT[64 * 76];          // transposed, padded
    __shared__ float sx[4 * IN_DIM];
    __shared__ float sas[64], sad[64];
    __shared__ float sWt[16], sbt[16];
    int tid = threadIdx.x;
    for (int i = tid; i < IN_DIM * 64; i += 256) {
        int k = i >> 6, j = i & 63;
        sWT[j * 76 + k] = W[i];
    }
    if (tid < 64) { sas[tid] = a_src[tid]; sad[tid] = a_dst[tid]; }
    if (TEMP && tid < 16) { sWt[tid] = Wt[tid]; sbt[tid] = bt[tid]; }
    __syncthreads();

    int lane = tid & 31;
    int node_local = tid >> 6;   // 0..3
    int j = tid & 63;            // output column
    const float* wrow = &sWT[j * 76];

    for (int g0 = blockIdx.x * 4; g0 < n; g0 += gridDim.x * 4) {
        __syncthreads();
        for (int i = tid; i < 4 * IN_DIM; i += 256) {
            int nl = i / IN_DIM, c = i % IN_DIM;
            int node = g0 + nl;
            float v = 0.0f;
            if (node < n) {
                if (TEMP) {
                    if (c < 56) v = in[(long)node * 56 + c];
                    else {
                        float t = tf[node] * sWt[c - 56] + sbt[c - 56];
                        v = t > 0.0f ? t : 0.0f;
                    }
                } else {
                    v = in[(long)node * IN_DIM + c];
                }
            }
            sx[nl * IN_DIM + c] = v;
        }
        __syncthreads();
        int node = g0 + node_local;
        if (node < n) {
            const float* xr = &sx[node_local * IN_DIM];
            float acc = 0.0f;
#pragma unroll
            for (int k = 0; k < IN_DIM; k += 4) {
                float4 wv = *(const float4*)&wrow[k];
                float4 xv = *(const float4*)&xr[k];
                acc = fmaf(wv.x, xv.x, acc);
                acc = fmaf(wv.y, xv.y, acc);
                acc = fmaf(wv.z, xv.z, acc);
                acc = fmaf(wv.w, xv.w, acc);
            }
            h_out[(long)node * 64 + j] = acc;
            float ps = acc * sas[j];
            float pd = acc * sad[j];
#pragma unroll
            for (int off = 8; off; off >>= 1) {
                ps += __shfl_down_sync(0xffffffffu, ps, off, 16);
                pd += __shfl_down_sync(0xffffffffu, pd, off, 16);
            }
            if ((lane & 15) == 0) {
                int head = j >> 4;
                s_out[node * 4 + head] = ps;
                d_out_[node * 4 + head] = pd;
            }
        }
    }
}

// ---------------- fused GAT aggregation + softmax-normalize + LN + ReLU ----------------
// Full warp per dst node: two 16-lane sub-halves process interleaved edges
// (stride 2), each unrolled x2 -> up to 4 independent gathers in flight.
// Lane (l = lane&15) owns 4 consecutive output columns. Self-loop analytic.
__global__ void gat_agg(const int* __restrict__ rowptr, const int* __restrict__ csrc,
                        const float* __restrict__ s_, const float* __restrict__ d_,
                        const float* __restrict__ h_,
                        const float* __restrict__ b,
                        const float* __restrict__ gma, const float* __restrict__ bta,
                        float* __restrict__ out, int n) {
    int lane = threadIdx.x & 31;
    int sub  = lane >> 4;       // 0 or 1
    int l    = lane & 15;
    int node = blockIdx.x * (blockDim.x >> 5) + (threadIdx.x >> 5);
    if (node >= n) return;
    int head = l >> 2;
    float dlog = d_[node * 4 + head];

    float4 acc = make_float4(0.f, 0.f, 0.f, 0.f);
    float z = 0.0f;
    if (sub == 0) {   // self-loop
        float w = __expf(lrelu(s_[node * 4 + head] + dlog));
        z = w;
        float4 hv = *(const float4*)&h_[(long)node * 64 + l * 4];
        acc = make_float4(w * hv.x, w * hv.y, w * hv.z, w * hv.w);
    }

    int beg = rowptr[node], end = rowptr[node + 1];
    int i = beg + sub;
    for (; i + 2 < end; i += 4) {
        int s0 = csrc[i];
        int s1 = csrc[i + 2];
        float e0 = s_[s0 * 4 + head];
        float e1 = s_[s1 * 4 + head];
        float4 h0 = *(const float4*)&h_[(long)s0 * 64 + l * 4];
        float4 h1 = *(const float4*)&h_[(long)s1 * 64 + l * 4];
        float w0 = __expf(lrelu(e0 + dlog));
        float w1 = __expf(lrelu(e1 + dlog));
        z += w0 + w1;
        acc.x = fmaf(w0, h0.x, acc.x); acc.x = fmaf(w1, h1.x, acc.x);
        acc.y = fmaf(w0, h0.y, acc.y); acc.y = fmaf(w1, h1.y, acc.y);
        acc.z = fmaf(w0, h0.z, acc.z); acc.z = fmaf(w1, h1.z, acc.z);
        acc.w = fmaf(w0, h0.w, acc.w); acc.w = fmaf(w1, h1.w, acc.w);
    }
    if (i < end) {
        int s0 = csrc[i];
        float w0 = __expf(lrelu(s_[s0 * 4 + head] + dlog));
        float4 h0 = *(const float4*)&h_[(long)s0 * 64 + l * 4];
        z += w0;
        acc.x = fmaf(w0, h0.x, acc.x);
        acc.y = fmaf(w0, h0.y, acc.y);
        acc.z = fmaf(w0, h0.z, acc.z);
        acc.w = fmaf(w0, h0.w, acc.w);
    }

    // combine the two sub-halves
    z     += __shfl_xor_sync(0xffffffffu, z, 16);
    acc.x += __shfl_xor_sync(0xffffffffu, acc.x, 16);
    acc.y += __shfl_xor_sync(0xffffffffu, acc.y, 16);
    acc.z += __shfl_xor_sync(0xffffffffu, acc.z, 16);
    acc.w += __shfl_xor_sync(0xffffffffu, acc.w, 16);

    float zinv = 1.0f / (z + 1e-16f);
    float4 v;
    v.x = acc.x * zinv + b[l * 4 + 0];
    v.y = acc.y * zinv + b[l * 4 + 1];
    v.z = acc.z * zinv + b[l * 4 + 2];
    v.w = acc.w * zinv + b[l * 4 + 3];

    float sum = v.x + v.y + v.z + v.w;
    float sq  = v.x * v.x + v.y * v.y + v.z * v.z + v.w * v.w;
#pragma unroll
    for (int off = 8; off; off >>= 1) {
        sum += __shfl_xor_sync(0xffffffffu, sum, off, 16);
        sq  += __shfl_xor_sync(0xffffffffu, sq, off, 16);
    }
    float mean = sum * (1.0f / 64.0f);
    float var  = sq * (1.0f / 64.0f) - mean * mean;
    float inv  = rsqrtf(var + LN_EPS);
    float4 o;
    o.x = (v.x - mean) * inv * gma[l * 4 + 0] + bta[l * 4 + 0];
    o.y = (v.y - mean) * inv * gma[l * 4 + 1] + bta[l * 4 + 1];
    o.z = (v.z - mean) * inv * gma[l * 4 + 2] + bta[l * 4 + 2];
    o.w = (v.w - mean) * inv * gma[l * 4 + 3] + bta[l * 4 + 3];
    o.x = o.x > 0.0f ? o.x : 0.0f;
    o.y = o.y > 0.0f ? o.y : 0.0f;
    o.z = o.z > 0.0f ? o.z : 0.0f;
    o.w = o.w > 0.0f ? o.w : 0.0f;
    if (sub == 0)
        *(float4*)&out[(long)node * 64 + l * 4] = o;
}

// ---------------- global mean (column sums) ----------------
__global__ void colsum(const float* __restrict__ x2, int n, float* __restrict__ acc) {
    int col = threadIdx.x & 63;
    int rowgrp = threadIdx.x >> 6;  // 0..3
    float s = 0.0f;
    for (int r = blockIdx.x * 4 + rowgrp; r < n; r += gridDim.x * 4)
        s += x2[(long)r * 64 + col];
    __shared__ float sm[256];
    sm[threadIdx.x] = s;
    __syncthreads();
    if (threadIdx.x < 64) {
        float t = sm[threadIdx.x] + sm[threadIdx.x + 64] +
                  sm[threadIdx.x + 128] + sm[threadIdx.x + 192];
        atomicAdd(&acc[threadIdx.x], t);
    }
}

// ---------------- final MLP on mean-pooled embedding ----------------
__global__ void final_mlp(const float* __restrict__ acc, int n,
                          const float* __restrict__ Wp1, const float* __restrict__ bp1,
                          const float* __restrict__ Wp2, const float* __restrict__ bp2,
                          float* __restrict__ out) {
    __shared__ float gein[64], hid[64];
    int t = threadIdx.x;  // 64 threads
    gein[t] = acc[t] / (float)n;
    __syncthreads();
    float a = bp1[t];
#pragma unroll
    for (int k = 0; k < 64; k++) a = fmaf(gein[k], Wp1[k * 64 + t], a);
    hid[t] = a > 0.0f ? a : 0.0f;
    __syncthreads();
    float o = bp2[t];
#pragma unroll
    for (int k = 0; k < 64; k++) o = fmaf(hid[k], Wp2[k * 64 + t], o);
    out[t] = o;
}

// ---------------- host launch ----------------
extern "C" void kernel_launch(void* const* d_in, const int* in_sizes, int n_in,
                              void* d_out, int out_size) {
    const float* x   = (const float*)d_in[0];
    const float* tf  = (const float*)d_in[1];
    const int*   ei  = (const int*)d_in[2];
    const float* Wt  = (const float*)d_in[3];
    const float* bt  = (const float*)d_in[4];
    const float* W1  = (const float*)d_in[5];
    const float* as1 = (const float*)d_in[6];
    const float* ad1 = (const float*)d_in[7];
    const float* b1  = (const float*)d_in[8];
    const float* g1  = (const float*)d_in[9];
    const float* be1 = (const float*)d_in[10];
    const float* W2  = (const float*)d_in[11];
    const float* as2 = (const float*)d_in[12];
    const float* ad2 = (const float*)d_in[13];
    const float* b2  = (const float*)d_in[14];
    const float* g2  = (const float*)d_in[15];
    const float* be2 = (const float*)d_in[16];
    const float* Wp1 = (const float*)d_in[17];
    const float* bp1 = (const float*)d_in[18];
    const float* Wp2 = (const float*)d_in[19];
    const float* bp2 = (const float*)d_in[20];

    int n = in_sizes[0] / 56;
    int E = in_sizes[2] / 2;

    float* out = (float*)d_out;
    float* x2  = out;              // [n, 64]
    float* ge  = out + (long)n * 64;

    float *h, *x1, *s, *d, *gacc;
    int *deg, *rowptr, *wptr, *csrc;
    cudaGetSymbolAddress((void**)&h,      g_h);
    cudaGetSymbolAddress((void**)&x1,     g_x1);
    cudaGetSymbolAddress((void**)&s,      g_s);
    cudaGetSymbolAddress((void**)&d,      g_d);
    cudaGetSymbolAddress((void**)&gacc,   g_gacc);
    cudaGetSymbolAddress((void**)&deg,    g_deg);
    cudaGetSymbolAddress((void**)&rowptr, g_rowptr);
    cudaGetSymbolAddress((void**)&wptr,   g_wptr);
    cudaGetSymbolAddress((void**)&csrc,   g_csrc);

    const int TB = 256;
    int ebk = (E + TB - 1) / TB;
    int nwb = (n + 7) / 8;       // warp-per-node blocks (8 nodes/block)

    // ---- CSR build (shared by both layers) ----
    filli<<<(n + TB - 1) / TB, TB>>>(deg, 0, n);
    hist_deg<<<ebk, TB>>>(ei, E, deg);
    scan_deg<<<1, 1024>>>(deg, n, rowptr, wptr);
    scatter_csr<<<ebk, TB>>>(ei, E, wptr, csrc);

    // ---- layer 1 (temporal concat fused into lin_att) ----
    lin_att<1, 72><<<2048, TB>>>(x, tf, Wt, bt, W1, as1, ad1, h, s, d, n);
    gat_agg<<<nwb, TB>>>(rowptr, csrc, s, d, h, b1, g1, be1, x1, n);

    // ---- layer 2 ----
    lin_att<0, 64><<<2048, TB>>>(x1, tf, Wt, bt, W2, as2, ad2, h, s, d, n);
    gat_agg<<<nwb, TB>>>(rowptr, csrc, s, d, h, b2, g2, be2, x2, n);

    // ---- global mean pool + MLP ----
    fillf<<<1, 64>>>(gacc, 0.0f, 64);
    colsum<<<1024, TB>>>(x2, n, gacc);
    final_mlp<<<1, 64>>>(gacc, n, Wp1, bp1, Wp2, bp2, ge);
}

// round 5
// speedup vs baseline: 1.5816x; 1.4756x over previous
#include <cuda_runtime.h>
#include <math.h>

#define NMAX 100000
#define EMAX 1600000
#define NEG_SLOPE 0.2f
#define LN_EPS 1e-5f
#define SCAN_CHUNK 512

// ---------------- scratch (device globals; no allocation) ----------------
__device__ float g_h[NMAX * 64];         // per-layer linear output (reused)
__device__ float g_x1[NMAX * 64];        // layer-1 output (input to layer 2)
__device__ float g_s[NMAX * 4];          // per-node src attention logits
__device__ float g_d[NMAX * 4];          // per-node dst attention logits
__device__ int   g_deg[NMAX];            // in-degree histogram
__device__ int   g_rowptr[NMAX + 1];     // CSR row pointers (by dst)
__device__ int   g_wptr[NMAX];           // scatter cursors
__device__ int   g_csrc[EMAX];           // CSR src ids
__device__ int   g_part[1024];           // scan partials
__device__ float g_gacc[64];             // column sums for global mean

__device__ __forceinline__ float lrelu(float v) {
    return v > 0.0f ? v : NEG_SLOPE * v;
}

// ---------------- small fills ----------------
__global__ void fillf(float* p, float v, int n) {
    int i = blockIdx.x * blockDim.x + threadIdx.x;
    if (i < n) p[i] = v;
}
__global__ void filli(int* p, int v, int n) {
    int i = blockIdx.x * blockDim.x + threadIdx.x;
    if (i < n) p[i] = v;
}

// ---------------- CSR build ----------------
__global__ void hist_deg(const int* __restrict__ ei, int E, int* __restrict__ deg) {
    int e = blockIdx.x * blockDim.x + threadIdx.x;
    if (e < E) atomicAdd(&deg[ei[E + e]], 1);
}

// scan stage A: per-block partial sums of deg (SCAN_CHUNK elements per block)
__global__ void scanA(const int* __restrict__ deg, int n, int* __restrict__ part) {
    __shared__ int sm[SCAN_CHUNK];
    int gid = blockIdx.x * SCAN_CHUNK + threadIdx.x;
    sm[threadIdx.x] = (gid < n) ? deg[gid] : 0;
    __syncthreads();
    for (int off = SCAN_CHUNK / 2; off > 0; off >>= 1) {
        if (threadIdx.x < off) sm[threadIdx.x] += sm[threadIdx.x + off];
        __syncthreads();
    }
    if (threadIdx.x == 0) part[blockIdx.x] = sm[0];
}

// scan stage B: single block scans <=1024 partials into exclusive offsets;
// writes total into rowptr[n].
__global__ void scanB(int* __restrict__ part, int nb, int n, int* __restrict__ rowptr) {
    __shared__ int sm[1024];
    int t = threadIdx.x;
    int v = (t < nb) ? part[t] : 0;
    sm[t] = v;
    __syncthreads();
    for (int off = 1; off < 1024; off <<= 1) {
        int add = (t >= off) ? sm[t - off] : 0;
        __syncthreads();
        sm[t] += add;
        __syncthreads();
    }
    if (t < nb) part[t] = sm[t] - v;          // exclusive
    if (t == 1023) rowptr[n] = sm[1023];      // total
}

// scan stage C: per-block exclusive scan of its chunk + block offset -> rowptr, wptr
__global__ void scanC(const int* __restrict__ deg, int n, const int* __restrict__ part,
                      int* __restrict__ rowptr, int* __restrict__ wptr) {
    __shared__ int sm[SCAN_CHUNK];
    int t = threadIdx.x;
    int gid = blockIdx.x * SCAN_CHUNK + t;
    int v = (gid < n) ? deg[gid] : 0;
    sm[t] = v;
    __syncthreads();
    for (int off = 1; off < SCAN_CHUNK; off <<= 1) {
        int add = (t >= off) ? sm[t - off] : 0;
        __syncthreads();
        sm[t] += add;
        __syncthreads();
    }
    if (gid < n) {
        int r = part[blockIdx.x] + sm[t] - v;
        rowptr[gid] = r;
        wptr[gid] = r;
    }
}

__global__ void scatter_csr(const int* __restrict__ ei, int E,
                            int* __restrict__ wptr, int* __restrict__ csrc) {
    int e = blockIdx.x * blockDim.x + threadIdx.x;
    if (e >= E) return;
    int d = ei[E + e];
    int pos = atomicAdd(&wptr[d], 1);
    csrc[pos] = ei[e];
}

// ---------------- fused linear + attention logits ----------------
// block = 256 threads = 4 nodes x 64 output cols.
// W transposed into smem [64][76]; x rows via float4 broadcast.
template <int TEMP, int IN_DIM>
__global__ void lin_att(const float* __restrict__ in,
                        const float* __restrict__ tf, const float* __restrict__ Wt,
                        const float* __restrict__ bt,
                        const float* __restrict__ W,
                        const float* __restrict__ a_src, const float* __restrict__ a_dst,
                        float* __restrict__ h_out, float* __restrict__ s_out,
                        float* __restrict__ d_out_, int n) {
    __shared__ float sWT[64 * 76];          // transposed, padded
    __shared__ float sx[4 * IN_DIM];
    __shared__ float sas[64], sad[64];
    __shared__ float sWt[16], sbt[16];
    int tid = threadIdx.x;
    for (int i = tid; i < IN_DIM * 64; i += 256) {
        int k = i >> 6, j = i & 63;
        sWT[j * 76 + k] = W[i];
    }
    if (tid < 64) { sas[tid] = a_src[tid]; sad[tid] = a_dst[tid]; }
    if (TEMP && tid < 16) { sWt[tid] = Wt[tid]; sbt[tid] = bt[tid]; }
    __syncthreads();

    int lane = tid & 31;
    int node_local = tid >> 6;   // 0..3
    int j = tid & 63;            // output column
    const float* wrow = &sWT[j * 76];

    for (int g0 = blockIdx.x * 4; g0 < n; g0 += gridDim.x * 4) {
        __syncthreads();
        for (int i = tid; i < 4 * IN_DIM; i += 256) {
            int nl = i / IN_DIM, c = i % IN_DIM;
            int node = g0 + nl;
            float v = 0.0f;
            if (node < n) {
                if (TEMP) {
                    if (c < 56) v = in[(long)node * 56 + c];
                    else {
                        float t = tf[node] * sWt[c - 56] + sbt[c - 56];
                        v = t > 0.0f ? t : 0.0f;
                    }
                } else {
                    v = in[(long)node * IN_DIM + c];
                }
            }
            sx[nl * IN_DIM + c] = v;
        }
        __syncthreads();
        int node = g0 + node_local;
        if (node < n) {
            const float* xr = &sx[node_local * IN_DIM];
            float acc = 0.0f;
#pragma unroll
            for (int k = 0; k < IN_DIM; k += 4) {
                float4 wv = *(const float4*)&wrow[k];
                float4 xv = *(const float4*)&xr[k];
                acc = fmaf(wv.x, xv.x, acc);
                acc = fmaf(wv.y, xv.y, acc);
                acc = fmaf(wv.z, xv.z, acc);
                acc = fmaf(wv.w, xv.w, acc);
            }
            h_out[(long)node * 64 + j] = acc;
            float ps = acc * sas[j];
            float pd = acc * sad[j];
#pragma unroll
            for (int off = 8; off; off >>= 1) {
                ps += __shfl_down_sync(0xffffffffu, ps, off, 16);
                pd += __shfl_down_sync(0xffffffffu, pd, off, 16);
            }
            if ((lane & 15) == 0) {
                int head = j >> 4;
                s_out[node * 4 + head] = ps;
                d_out_[node * 4 + head] = pd;
            }
        }
    }
}

// ---------------- fused GAT aggregation + softmax-normalize + LN + ReLU ----------------
// Full warp per dst node: two 16-lane sub-halves on interleaved edges, each
// unrolled x4 -> up to 8 independent gathers in flight per warp.
__global__ void gat_agg(const int* __restrict__ rowptr, const int* __restrict__ csrc,
                        const float* __restrict__ s_, const float* __restrict__ d_,
                        const float* __restrict__ h_,
                        const float* __restrict__ b,
                        const float* __restrict__ gma, const float* __restrict__ bta,
                        float* __restrict__ out, int n) {
    int lane = threadIdx.x & 31;
    int sub  = lane >> 4;       // 0 or 1
    int l    = lane & 15;
    int node = blockIdx.x * (blockDim.x >> 5) + (threadIdx.x >> 5);
    if (node >= n) return;
    int head = l >> 2;
    float dlog = d_[node * 4 + head];

    float4 acc = make_float4(0.f, 0.f, 0.f, 0.f);
    float z = 0.0f;
    if (sub == 0) {   // self-loop
        float w = __expf(lrelu(s_[node * 4 + head] + dlog));
        z = w;
        float4 hv = *(const float4*)&h_[(long)node * 64 + l * 4];
        acc = make_float4(w * hv.x, w * hv.y, w * hv.z, w * hv.w);
    }

    int beg = rowptr[node], end = rowptr[node + 1];
    int i = beg + sub;
    for (; i + 6 < end; i += 8) {
        int s0 = csrc[i];
        int s1 = csrc[i + 2];
        int s2 = csrc[i + 4];
        int s3 = csrc[i + 6];
        float e0 = s_[s0 * 4 + head];
        float e1 = s_[s1 * 4 + head];
        float e2 = s_[s2 * 4 + head];
        float e3 = s_[s3 * 4 + head];
        float4 h0 = *(const float4*)&h_[(long)s0 * 64 + l * 4];
        float4 h1 = *(const float4*)&h_[(long)s1 * 64 + l * 4];
        float4 h2 = *(const float4*)&h_[(long)s2 * 64 + l * 4];
        float4 h3 = *(const float4*)&h_[(long)s3 * 64 + l * 4];
        float w0 = __expf(lrelu(e0 + dlog));
        float w1 = __expf(lrelu(e1 + dlog));
        float w2 = __expf(lrelu(e2 + dlog));
        float w3 = __expf(lrelu(e3 + dlog));
        z += (w0 + w1) + (w2 + w3);
        acc.x = fmaf(w0, h0.x, acc.x); acc.x = fmaf(w1, h1.x, acc.x);
        acc.x = fmaf(w2, h2.x, acc.x); acc.x = fmaf(w3, h3.x, acc.x);
        acc.y = fmaf(w0, h0.y, acc.y); acc.y = fmaf(w1, h1.y, acc.y);
        acc.y = fmaf(w2, h2.y, acc.y); acc.y = fmaf(w3, h3.y, acc.y);
        acc.z = fmaf(w0, h0.z, acc.z); acc.z = fmaf(w1, h1.z, acc.z);
        acc.z = fmaf(w2, h2.z, acc.z); acc.z = fmaf(w3, h3.z, acc.z);
        acc.w = fmaf(w0, h0.w, acc.w); acc.w = fmaf(w1, h1.w, acc.w);
        acc.w = fmaf(w2, h2.w, acc.w); acc.w = fmaf(w3, h3.w, acc.w);
    }
    for (; i < end; i += 2) {
        int s0 = csrc[i];
        float w0 = __expf(lrelu(s_[s0 * 4 + head] + dlog));
        float4 h0 = *(const float4*)&h_[(long)s0 * 64 + l * 4];
        z += w0;
        acc.x = fmaf(w0, h0.x, acc.x);
        acc.y = fmaf(w0, h0.y, acc.y);
        acc.z = fmaf(w0, h0.z, acc.z);
        acc.w = fmaf(w0, h0.w, acc.w);
    }

    // combine the two sub-halves
    z     += __shfl_xor_sync(0xffffffffu, z, 16);
    acc.x += __shfl_xor_sync(0xffffffffu, acc.x, 16);
    acc.y += __shfl_xor_sync(0xffffffffu, acc.y, 16);
    acc.z += __shfl_xor_sync(0xffffffffu, acc.z, 16);
    acc.w += __shfl_xor_sync(0xffffffffu, acc.w, 16);

    float zinv = 1.0f / (z + 1e-16f);
    float4 v;
    v.x = acc.x * zinv + b[l * 4 + 0];
    v.y = acc.y * zinv + b[l * 4 + 1];
    v.z = acc.z * zinv + b[l * 4 + 2];
    v.w = acc.w * zinv + b[l * 4 + 3];

    float sum = v.x + v.y + v.z + v.w;
    float sq  = v.x * v.x + v.y * v.y + v.z * v.z + v.w * v.w;
#pragma unroll
    for (int off = 8; off; off >>= 1) {
        sum += __shfl_xor_sync(0xffffffffu, sum, off, 16);
        sq  += __shfl_xor_sync(0xffffffffu, sq, off, 16);
    }
    float mean = sum * (1.0f / 64.0f);
    float var  = sq * (1.0f / 64.0f) - mean * mean;
    float inv  = rsqrtf(var + LN_EPS);
    float4 o;
    o.x = (v.x - mean) * inv * gma[l * 4 + 0] + bta[l * 4 + 0];
    o.y = (v.y - mean) * inv * gma[l * 4 + 1] + bta[l * 4 + 1];
    o.z = (v.z - mean) * inv * gma[l * 4 + 2] + bta[l * 4 + 2];
    o.w = (v.w - mean) * inv * gma[l * 4 + 3] + bta[l * 4 + 3];
    o.x = o.x > 0.0f ? o.x : 0.0f;
    o.y = o.y > 0.0f ? o.y : 0.0f;
    o.z = o.z > 0.0f ? o.z : 0.0f;
    o.w = o.w > 0.0f ? o.w : 0.0f;
    if (sub == 0)
        *(float4*)&out[(long)node * 64 + l * 4] = o;
}

// ---------------- global mean (column sums) ----------------
__global__ void colsum(const float* __restrict__ x2, int n, float* __restrict__ acc) {
    int col = threadIdx.x & 63;
    int rowgrp = threadIdx.x >> 6;  // 0..3
    float s = 0.0f;
    for (int r = blockIdx.x * 4 + rowgrp; r < n; r += gridDim.x * 4)
        s += x2[(long)r * 64 + col];
    __shared__ float sm[256];
    sm[threadIdx.x] = s;
    __syncthreads();
    if (threadIdx.x < 64) {
        float t = sm[threadIdx.x] + sm[threadIdx.x + 64] +
                  sm[threadIdx.x + 128] + sm[threadIdx.x + 192];
        atomicAdd(&acc[threadIdx.x], t);
    }
}

// ---------------- final MLP on mean-pooled embedding ----------------
__global__ void final_mlp(const float* __restrict__ acc, int n,
                          const float* __restrict__ Wp1, const float* __restrict__ bp1,
                          const float* __restrict__ Wp2, const float* __restrict__ bp2,
                          float* __restrict__ out) {
    __shared__ float gein[64], hid[64];
    int t = threadIdx.x;  // 64 threads
    gein[t] = acc[t] / (float)n;
    __syncthreads();
    float a = bp1[t];
#pragma unroll
    for (int k = 0; k < 64; k++) a = fmaf(gein[k], Wp1[k * 64 + t], a);
    hid[t] = a > 0.0f ? a : 0.0f;
    __syncthreads();
    float o = bp2[t];
#pragma unroll
    for (int k = 0; k < 64; k++) o = fmaf(hid[k], Wp2[k * 64 + t], o);
    out[t] = o;
}

// ---------------- host launch ----------------
extern "C" void kernel_launch(void* const* d_in, const int* in_sizes, int n_in,
                              void* d_out, int out_size) {
    const float* x   = (const float*)d_in[0];
    const float* tf  = (const float*)d_in[1];
    const int*   ei  = (const int*)d_in[2];
    const float* Wt  = (const float*)d_in[3];
    const float* bt  = (const float*)d_in[4];
    const float* W1  = (const float*)d_in[5];
    const float* as1 = (const float*)d_in[6];
    const float* ad1 = (const float*)d_in[7];
    const float* b1  = (const float*)d_in[8];
    const float* g1  = (const float*)d_in[9];
    const float* be1 = (const float*)d_in[10];
    const float* W2  = (const float*)d_in[11];
    const float* as2 = (const float*)d_in[12];
    const float* ad2 = (const float*)d_in[13];
    const float* b2  = (const float*)d_in[14];
    const float* g2  = (const float*)d_in[15];
    const float* be2 = (const float*)d_in[16];
    const float* Wp1 = (const float*)d_in[17];
    const float* bp1 = (const float*)d_in[18];
    const float* Wp2 = (const float*)d_in[19];
    const float* bp2 = (const float*)d_in[20];

    int n = in_sizes[0] / 56;
    int E = in_sizes[2] / 2;

    float* out = (float*)d_out;
    float* x2  = out;              // [n, 64]
    float* ge  = out + (long)n * 64;

    float *h, *x1, *s, *d, *gacc;
    int *deg, *rowptr, *wptr, *csrc, *part;
    cudaGetSymbolAddress((void**)&h,      g_h);
    cudaGetSymbolAddress((void**)&x1,     g_x1);
    cudaGetSymbolAddress((void**)&s,      g_s);
    cudaGetSymbolAddress((void**)&d,      g_d);
    cudaGetSymbolAddress((void**)&gacc,   g_gacc);
    cudaGetSymbolAddress((void**)&deg,    g_deg);
    cudaGetSymbolAddress((void**)&rowptr, g_rowptr);
    cudaGetSymbolAddress((void**)&wptr,   g_wptr);
    cudaGetSymbolAddress((void**)&csrc,   g_csrc);
    cudaGetSymbolAddress((void**)&part,   g_part);

    const int TB = 256;
    int ebk = (E + TB - 1) / TB;
    int nwb = (n + 7) / 8;                       // warp-per-node blocks
    int nsb = (n + SCAN_CHUNK - 1) / SCAN_CHUNK; // scan blocks (<=1024)

    // ---- CSR build (interleaved with layer-1 linear so launch #4 = lin_att) ----
    filli<<<(n + TB - 1) / TB, TB>>>(deg, 0, n);              // 1
    hist_deg<<<ebk, TB>>>(ei, E, deg);                        // 2
    scanA<<<nsb, SCAN_CHUNK>>>(deg, n, part);                 // 3
    lin_att<1, 72><<<2048, TB>>>(x, tf, Wt, bt, W1, as1, ad1, h, s, d, n);  // 4 (profiled)
    scanB<<<1, 1024>>>(part, nsb, n, rowptr);                 // 5
    scanC<<<nsb, SCAN_CHUNK>>>(deg, n, part, rowptr, wptr);   // 6
    scatter_csr<<<ebk, TB>>>(ei, E, wptr, csrc);              // 7

    // ---- layer 1 aggregation ----
    gat_agg<<<nwb, TB>>>(rowptr, csrc, s, d, h, b1, g1, be1, x1, n);

    // ---- layer 2 ----
    lin_att<0, 64><<<2048, TB>>>(x1, tf, Wt, bt, W2, as2, ad2, h, s, d, n);
    gat_agg<<<nwb, TB>>>(rowptr, csrc, s, d, h, b2, g2, be2, x2, n);

    // ---- global mean pool + MLP ----
    fillf<<<1, 64>>>(gacc, 0.0f, 64);
    colsum<<<1024, TB>>>(x2, n, gacc);
    final_mlp<<<1, 64>>>(gacc, n, Wp1, bp1, Wp2, bp2, ge);
}

// round 6
// speedup vs baseline: 1.8254x; 1.1542x over previous
#include <cuda_runtime.h>
#include <math.h>

#define NMAX 100000
#define EMAX 1600000
#define NEG_SLOPE 0.2f
#define LN_EPS 1e-5f
#define SCAN_CHUNK 512

// ---------------- scratch (device globals; no allocation) ----------------
__device__ float g_h[NMAX * 64];         // per-layer linear output (reused)
__device__ float g_x1[NMAX * 64];        // layer-1 output (input to layer 2)
__device__ float g_s[NMAX * 4];          // per-node src attention logits
__device__ float g_d[NMAX * 4];          // per-node dst attention logits
__device__ int   g_deg[NMAX];            // in-degree histogram
__device__ int   g_rowptr[NMAX + 1];     // CSR row pointers (by dst)
__device__ int   g_wptr[NMAX];           // scatter cursors
__device__ int   g_csrc[EMAX];           // CSR src ids
__device__ int   g_part[1024];           // scan partials
__device__ float g_gacc[64];             // column sums for global mean

__device__ __forceinline__ float lrelu(float v) {
    return v > 0.0f ? v : NEG_SLOPE * v;
}

// ---------------- small fills ----------------
__global__ void fillf(float* p, float v, int n) {
    int i = blockIdx.x * blockDim.x + threadIdx.x;
    if (i < n) p[i] = v;
}
__global__ void filli(int* p, int v, int n) {
    int i = blockIdx.x * blockDim.x + threadIdx.x;
    if (i < n) p[i] = v;
}

// ---------------- CSR build ----------------
__global__ void hist_deg(const int* __restrict__ ei, int E, int* __restrict__ deg) {
    int e = blockIdx.x * blockDim.x + threadIdx.x;
    if (e < E) atomicAdd(&deg[ei[E + e]], 1);
}

// scan stage A: per-block partial sums of deg
__global__ void scanA(const int* __restrict__ deg, int n, int* __restrict__ part) {
    __shared__ int sm[SCAN_CHUNK];
    int gid = blockIdx.x * SCAN_CHUNK + threadIdx.x;
    sm[threadIdx.x] = (gid < n) ? deg[gid] : 0;
    __syncthreads();
    for (int off = SCAN_CHUNK / 2; off > 0; off >>= 1) {
        if (threadIdx.x < off) sm[threadIdx.x] += sm[threadIdx.x + off];
        __syncthreads();
    }
    if (threadIdx.x == 0) part[blockIdx.x] = sm[0];
}

// scan stage B: single block scans <=1024 partials into exclusive offsets
__global__ void scanB(int* __restrict__ part, int nb, int n, int* __restrict__ rowptr) {
    __shared__ int sm[1024];
    int t = threadIdx.x;
    int v = (t < nb) ? part[t] : 0;
    sm[t] = v;
    __syncthreads();
    for (int off = 1; off < 1024; off <<= 1) {
        int add = (t >= off) ? sm[t - off] : 0;
        __syncthreads();
        sm[t] += add;
        __syncthreads();
    }
    if (t < nb) part[t] = sm[t] - v;          // exclusive
    if (t == 1023) rowptr[n] = sm[1023];      // total
}

// scan stage C: per-block exclusive scan + block offset -> rowptr, wptr
__global__ void scanC(const int* __restrict__ deg, int n, const int* __restrict__ part,
                      int* __restrict__ rowptr, int* __restrict__ wptr) {
    __shared__ int sm[SCAN_CHUNK];
    int t = threadIdx.x;
    int gid = blockIdx.x * SCAN_CHUNK + t;
    int v = (gid < n) ? deg[gid] : 0;
    sm[t] = v;
    __syncthreads();
    for (int off = 1; off < SCAN_CHUNK; off <<= 1) {
        int add = (t >= off) ? sm[t - off] : 0;
        __syncthreads();
        sm[t] += add;
        __syncthreads();
    }
    if (gid < n) {
        int r = part[blockIdx.x] + sm[t] - v;
        rowptr[gid] = r;
        wptr[gid] = r;
    }
}

__global__ void scatter_csr(const int* __restrict__ ei, int E,
                            int* __restrict__ wptr, int* __restrict__ csrc) {
    int e = blockIdx.x * blockDim.x + threadIdx.x;
    if (e >= E) return;
    int d = ei[E + e];
    int pos = atomicAdd(&wptr[d], 1);
    csrc[pos] = ei[e];
}

// ---------------- fused linear + attention logits ----------------
// block = 256 threads = 64 output cols x 4 groups; each group handles 8 nodes
// per outer iteration (32 nodes/block-iter). Each thread keeps its W column
// in REGISTERS (loaded once, coalesced); x rows broadcast from smem.
template <int TEMP, int IN_DIM>
__global__ void __launch_bounds__(256, 2)
lin_att(const float* __restrict__ in,
        const float* __restrict__ tf, const float* __restrict__ Wt,
        const float* __restrict__ bt,
        const float* __restrict__ W,
        const float* __restrict__ a_src, const float* __restrict__ a_dst,
        float* __restrict__ h_out, float* __restrict__ s_out,
        float* __restrict__ d_out_, int n) {
    __shared__ float sx[32 * IN_DIM];
    __shared__ float sWt[16], sbt[16];
    int tid = threadIdx.x;
    if (TEMP && tid < 16) { sWt[tid] = Wt[tid]; sbt[tid] = bt[tid]; }

    int lane = tid & 31;
    int group = tid >> 6;        // 0..3
    int j = tid & 63;            // output column

    // W column in registers (coalesced loads: consecutive j)
    float wreg[IN_DIM];
#pragma unroll
    for (int k = 0; k < IN_DIM; k++) wreg[k] = W[k * 64 + j];
    float asj = a_src[j], adj = a_dst[j];

    for (int g0 = blockIdx.x * 32; g0 < n; g0 += gridDim.x * 32) {
        __syncthreads();
        for (int i = tid; i < 32 * IN_DIM; i += 256) {
            int nl = i / IN_DIM, c = i % IN_DIM;
            int node = g0 + nl;
            float v = 0.0f;
            if (node < n) {
                if (TEMP) {
                    if (c < 56) v = in[(long)node * 56 + c];
                    else {
                        float t = tf[node] * sWt[c - 56] + sbt[c - 56];
                        v = t > 0.0f ? t : 0.0f;
                    }
                } else {
                    v = in[(long)node * IN_DIM + c];
                }
            }
            sx[nl * IN_DIM + c] = v;
        }
        __syncthreads();

        float acc[8];
#pragma unroll
        for (int r = 0; r < 8; r++) acc[r] = 0.0f;
        const float* xbase = &sx[(group * 8) * IN_DIM];
#pragma unroll
        for (int k = 0; k < IN_DIM; k += 4) {
            float4 xv[8];
#pragma unroll
            for (int r = 0; r < 8; r++)
                xv[r] = *(const float4*)&xbase[r * IN_DIM + k];
#pragma unroll
            for (int r = 0; r < 8; r++) {
                acc[r] = fmaf(wreg[k + 0], xv[r].x, acc[r]);
                acc[r] = fmaf(wreg[k + 1], xv[r].y, acc[r]);
                acc[r] = fmaf(wreg[k + 2], xv[r].z, acc[r]);
                acc[r] = fmaf(wreg[k + 3], xv[r].w, acc[r]);
            }
        }

#pragma unroll
        for (int r = 0; r < 8; r++) {
            int node = g0 + group * 8 + r;
            if (node < n) {
                h_out[(long)node * 64 + j] = acc[r];
                float ps = acc[r] * asj;
                float pd = acc[r] * adj;
#pragma unroll
                for (int off = 8; off; off >>= 1) {
                    ps += __shfl_down_sync(0xffffffffu, ps, off, 16);
                    pd += __shfl_down_sync(0xffffffffu, pd, off, 16);
                }
                if ((lane & 15) == 0) {
                    int head = j >> 4;
                    s_out[node * 4 + head] = ps;
                    d_out_[node * 4 + head] = pd;
                }
            }
        }
    }
}

// ---------------- fused GAT aggregation + softmax-normalize + LN + ReLU ----------------
// Full warp per dst node: two 16-lane sub-halves on interleaved edges, each
// unrolled x4 -> up to 8 independent gathers in flight per warp.
__global__ void gat_agg(const int* __restrict__ rowptr, const int* __restrict__ csrc,
                        const float* __restrict__ s_, const float* __restrict__ d_,
                        const float* __restrict__ h_,
                        const float* __restrict__ b,
                        const float* __restrict__ gma, const float* __restrict__ bta,
                        float* __restrict__ out, int n) {
    int lane = threadIdx.x & 31;
    int sub  = lane >> 4;       // 0 or 1
    int l    = lane & 15;
    int node = blockIdx.x * (blockDim.x >> 5) + (threadIdx.x >> 5);
    if (node >= n) return;
    int head = l >> 2;
    float dlog = d_[node * 4 + head];

    float4 acc = make_float4(0.f, 0.f, 0.f, 0.f);
    float z = 0.0f;
    if (sub == 0) {   // self-loop
        float w = __expf(lrelu(s_[node * 4 + head] + dlog));
        z = w;
        float4 hv = *(const float4*)&h_[(long)node * 64 + l * 4];
        acc = make_float4(w * hv.x, w * hv.y, w * hv.z, w * hv.w);
    }

    int beg = rowptr[node], end = rowptr[node + 1];
    int i = beg + sub;
    for (; i + 6 < end; i += 8) {
        int s0 = csrc[i];
        int s1 = csrc[i + 2];
        int s2 = csrc[i + 4];
        int s3 = csrc[i + 6];
        float e0 = s_[s0 * 4 + head];
        float e1 = s_[s1 * 4 + head];
        float e2 = s_[s2 * 4 + head];
        float e3 = s_[s3 * 4 + head];
        float4 h0 = *(const float4*)&h_[(long)s0 * 64 + l * 4];
        float4 h1 = *(const float4*)&h_[(long)s1 * 64 + l * 4];
        float4 h2 = *(const float4*)&h_[(long)s2 * 64 + l * 4];
        float4 h3 = *(const float4*)&h_[(long)s3 * 64 + l * 4];
        float w0 = __expf(lrelu(e0 + dlog));
        float w1 = __expf(lrelu(e1 + dlog));
        float w2 = __expf(lrelu(e2 + dlog));
        float w3 = __expf(lrelu(e3 + dlog));
        z += (w0 + w1) + (w2 + w3);
        acc.x = fmaf(w0, h0.x, acc.x); acc.x = fmaf(w1, h1.x, acc.x);
        acc.x = fmaf(w2, h2.x, acc.x); acc.x = fmaf(w3, h3.x, acc.x);
        acc.y = fmaf(w0, h0.y, acc.y); acc.y = fmaf(w1, h1.y, acc.y);
        acc.y = fmaf(w2, h2.y, acc.y); acc.y = fmaf(w3, h3.y, acc.y);
        acc.z = fmaf(w0, h0.z, acc.z); acc.z = fmaf(w1, h1.z, acc.z);
        acc.z = fmaf(w2, h2.z, acc.z); acc.z = fmaf(w3, h3.z, acc.z);
        acc.w = fmaf(w0, h0.w, acc.w); acc.w = fmaf(w1, h1.w, acc.w);
        acc.w = fmaf(w2, h2.w, acc.w); acc.w = fmaf(w3, h3.w, acc.w);
    }
    for (; i < end; i += 2) {
        int s0 = csrc[i];
        float w0 = __expf(lrelu(s_[s0 * 4 + head] + dlog));
        float4 h0 = *(const float4*)&h_[(long)s0 * 64 + l * 4];
        z += w0;
        acc.x = fmaf(w0, h0.x, acc.x);
        acc.y = fmaf(w0, h0.y, acc.y);
        acc.z = fmaf(w0, h0.z, acc.z);
        acc.w = fmaf(w0, h0.w, acc.w);
    }

    // combine the two sub-halves
    z     += __shfl_xor_sync(0xffffffffu, z, 16);
    acc.x += __shfl_xor_sync(0xffffffffu, acc.x, 16);
    acc.y += __shfl_xor_sync(0xffffffffu, acc.y, 16);
    acc.z += __shfl_xor_sync(0xffffffffu, acc.z, 16);
    acc.w += __shfl_xor_sync(0xffffffffu, acc.w, 16);

    float zinv = 1.0f / (z + 1e-16f);
    float4 v;
    v.x = acc.x * zinv + b[l * 4 + 0];
    v.y = acc.y * zinv + b[l * 4 + 1];
    v.z = acc.z * zinv + b[l * 4 + 2];
    v.w = acc.w * zinv + b[l * 4 + 3];

    float sum = v.x + v.y + v.z + v.w;
    float sq  = v.x * v.x + v.y * v.y + v.z * v.z + v.w * v.w;
#pragma unroll
    for (int off = 8; off; off >>= 1) {
        sum += __shfl_xor_sync(0xffffffffu, sum, off, 16);
        sq  += __shfl_xor_sync(0xffffffffu, sq, off, 16);
    }
    float mean = sum * (1.0f / 64.0f);
    float var  = sq * (1.0f / 64.0f) - mean * mean;
    float inv  = rsqrtf(var + LN_EPS);
    float4 o;
    o.x = (v.x - mean) * inv * gma[l * 4 + 0] + bta[l * 4 + 0];
    o.y = (v.y - mean) * inv * gma[l * 4 + 1] + bta[l * 4 + 1];
    o.z = (v.z - mean) * inv * gma[l * 4 + 2] + bta[l * 4 + 2];
    o.w = (v.w - mean) * inv * gma[l * 4 + 3] + bta[l * 4 + 3];
    o.x = o.x > 0.0f ? o.x : 0.0f;
    o.y = o.y > 0.0f ? o.y : 0.0f;
    o.z = o.z > 0.0f ? o.z : 0.0f;
    o.w = o.w > 0.0f ? o.w : 0.0f;
    if (sub == 0)
        *(float4*)&out[(long)node * 64 + l * 4] = o;
}

// ---------------- global mean (column sums) ----------------
__global__ void colsum(const float* __restrict__ x2, int n, float* __restrict__ acc) {
    int col = threadIdx.x & 63;
    int rowgrp = threadIdx.x >> 6;  // 0..3
    float s = 0.0f;
    for (int r = blockIdx.x * 4 + rowgrp; r < n; r += gridDim.x * 4)
        s += x2[(long)r * 64 + col];
    __shared__ float sm[256];
    sm[threadIdx.x] = s;
    __syncthreads();
    if (threadIdx.x < 64) {
        float t = sm[threadIdx.x] + sm[threadIdx.x + 64] +
                  sm[threadIdx.x + 128] + sm[threadIdx.x + 192];
        atomicAdd(&acc[threadIdx.x], t);
    }
}

// ---------------- final MLP on mean-pooled embedding ----------------
__global__ void final_mlp(const float* __restrict__ acc, int n,
                          const float* __restrict__ Wp1, const float* __restrict__ bp1,
                          const float* __restrict__ Wp2, const float* __restrict__ bp2,
                          float* __restrict__ out) {
    __shared__ float gein[64], hid[64];
    int t = threadIdx.x;  // 64 threads
    gein[t] = acc[t] / (float)n;
    __syncthreads();
    float a = bp1[t];
#pragma unroll
    for (int k = 0; k < 64; k++) a = fmaf(gein[k], Wp1[k * 64 + t], a);
    hid[t] = a > 0.0f ? a : 0.0f;
    __syncthreads();
    float o = bp2[t];
#pragma unroll
    for (int k = 0; k < 64; k++) o = fmaf(hid[k], Wp2[k * 64 + t], o);
    out[t] = o;
}

// ---------------- host launch ----------------
extern "C" void kernel_launch(void* const* d_in, const int* in_sizes, int n_in,
                              void* d_out, int out_size) {
    const float* x   = (const float*)d_in[0];
    const float* tf  = (const float*)d_in[1];
    const int*   ei  = (const int*)d_in[2];
    const float* Wt  = (const float*)d_in[3];
    const float* bt  = (const float*)d_in[4];
    const float* W1  = (const float*)d_in[5];
    const float* as1 = (const float*)d_in[6];
    const float* ad1 = (const float*)d_in[7];
    const float* b1  = (const float*)d_in[8];
    const float* g1  = (const float*)d_in[9];
    const float* be1 = (const float*)d_in[10];
    const float* W2  = (const float*)d_in[11];
    const float* as2 = (const float*)d_in[12];
    const float* ad2 = (const float*)d_in[13];
    const float* b2  = (const float*)d_in[14];
    const float* g2  = (const float*)d_in[15];
    const float* be2 = (const float*)d_in[16];
    const float* Wp1 = (const float*)d_in[17];
    const float* bp1 = (const float*)d_in[18];
    const float* Wp2 = (const float*)d_in[19];
    const float* bp2 = (const float*)d_in[20];

    int n = in_sizes[0] / 56;
    int E = in_sizes[2] / 2;

    float* out = (float*)d_out;
    float* x2  = out;              // [n, 64]
    float* ge  = out + (long)n * 64;

    float *h, *x1, *s, *d, *gacc;
    int *deg, *rowptr, *wptr, *csrc, *part;
    cudaGetSymbolAddress((void**)&h,      g_h);
    cudaGetSymbolAddress((void**)&x1,     g_x1);
    cudaGetSymbolAddress((void**)&s,      g_s);
    cudaGetSymbolAddress((void**)&d,      g_d);
    cudaGetSymbolAddress((void**)&gacc,   g_gacc);
    cudaGetSymbolAddress((void**)&deg,    g_deg);
    cudaGetSymbolAddress((void**)&rowptr, g_rowptr);
    cudaGetSymbolAddress((void**)&wptr,   g_wptr);
    cudaGetSymbolAddress((void**)&csrc,   g_csrc);
    cudaGetSymbolAddress((void**)&part,   g_part);

    const int TB = 256;
    int ebk = (E + TB - 1) / TB;
    int nwb = (n + 7) / 8;                       // warp-per-node blocks
    int nsb = (n + SCAN_CHUNK - 1) / SCAN_CHUNK; // scan blocks (<=1024)
    int lgb = (n + 31) / 32;                     // lin_att blocks needed
    if (lgb > 2048) lgb = 2048;

    // ---- CSR build (launch #4 = lin_att<1> for profiling) ----
    filli<<<(n + TB - 1) / TB, TB>>>(deg, 0, n);              // 1
    hist_deg<<<ebk, TB>>>(ei, E, deg);                        // 2
    scanA<<<nsb, SCAN_CHUNK>>>(deg, n, part);                 // 3
    lin_att<1, 72><<<lgb, TB>>>(x, tf, Wt, bt, W1, as1, ad1, h, s, d, n);  // 4 (profiled)
    scanB<<<1, 1024>>>(part, nsb, n, rowptr);                 // 5
    scanC<<<nsb, SCAN_CHUNK>>>(deg, n, part, rowptr, wptr);   // 6
    scatter_csr<<<ebk, TB>>>(ei, E, wptr, csrc);              // 7

    // ---- layer 1 aggregation ----
    gat_agg<<<nwb, TB>>>(rowptr, csrc, s, d, h, b1, g1, be1, x1, n);

    // ---- layer 2 ----
    lin_att<0, 64><<<lgb, TB>>>(x1, tf, Wt, bt, W2, as2, ad2, h, s, d, n);
    gat_agg<<<nwb, TB>>>(rowptr, csrc, s, d, h, b2, g2, be2, x2, n);

    // ---- global mean pool + MLP ----
    fillf<<<1, 64>>>(gacc, 0.0f, 64);
    colsum<<<1024, TB>>>(x2, n, gacc);
    final_mlp<<<1, 64>>>(gacc, n, Wp1, bp1, Wp2, bp2, ge);
}

// round 7
// speedup vs baseline: 1.8351x; 1.0053x over previous
#include <cuda_runtime.h>
#include <math.h>

#define NMAX 100000
#define EMAX 1600000
#define NEG_SLOPE 0.2f
#define LN_EPS 1e-5f
#define SCAN_CHUNK 512

// ---------------- scratch (device globals; no allocation) ----------------
__device__ __align__(16) float g_h[NMAX * 64];   // per-layer linear output
__device__ __align__(16) float g_x1[NMAX * 64];  // layer-1 output
__device__ __align__(16) float g_s[NMAX * 4];    // per-node src logits
__device__ __align__(16) float g_d[NMAX * 4];    // per-node dst logits
__device__ __align__(16) float g_ws[8 * 72];     // folded attention weights
__device__ int   g_deg[NMAX];
__device__ int   g_rowptr[NMAX + 1];
__device__ int   g_wptr[NMAX];
__device__ int   g_csrc[EMAX];
__device__ int   g_part[1024];
__device__ float g_gacc[64];

__device__ __forceinline__ float lrelu(float v) {
    return v > 0.0f ? v : NEG_SLOPE * v;
}

// ---------------- cp.async helpers ----------------
__device__ __forceinline__ unsigned smem_u32(const void* p) {
    return (unsigned)__cvta_generic_to_shared(p);
}
__device__ __forceinline__ void cp16(void* dst, const void* src) {
    asm volatile("cp.async.cg.shared.global [%0], [%1], 16;"
                 :: "r"(smem_u32(dst)), "l"(src));
}
__device__ __forceinline__ void cp_commit() {
    asm volatile("cp.async.commit_group;" ::: "memory");
}
template <int N>
__device__ __forceinline__ void cp_wait() {
    asm volatile("cp.async.wait_group %0;" :: "n"(N) : "memory");
}

// ---------------- small fills ----------------
__global__ void fillf(float* p, float v, int n) {
    int i = blockIdx.x * blockDim.x + threadIdx.x;
    if (i < n) p[i] = v;
}
__global__ void filli(int* p, int v, int n) {
    int i = blockIdx.x * blockDim.x + threadIdx.x;
    if (i < n) p[i] = v;
}

// ---------------- CSR build ----------------
__global__ void hist_deg(const int* __restrict__ ei, int E, int* __restrict__ deg) {
    int e = blockIdx.x * blockDim.x + threadIdx.x;
    if (e < E) atomicAdd(&deg[ei[E + e]], 1);
}

__global__ void scanA(const int* __restrict__ deg, int n, int* __restrict__ part) {
    __shared__ int sm[SCAN_CHUNK];
    int gid = blockIdx.x * SCAN_CHUNK + threadIdx.x;
    sm[threadIdx.x] = (gid < n) ? deg[gid] : 0;
    __syncthreads();
    for (int off = SCAN_CHUNK / 2; off > 0; off >>= 1) {
        if (threadIdx.x < off) sm[threadIdx.x] += sm[threadIdx.x + off];
        __syncthreads();
    }
    if (threadIdx.x == 0) part[blockIdx.x] = sm[0];
}

__global__ void scanB(int* __restrict__ part, int nb, int n, int* __restrict__ rowptr) {
    __shared__ int sm[1024];
    int t = threadIdx.x;
    int v = (t < nb) ? part[t] : 0;
    sm[t] = v;
    __syncthreads();
    for (int off = 1; off < 1024; off <<= 1) {
        int add = (t >= off) ? sm[t - off] : 0;
        __syncthreads();
        sm[t] += add;
        __syncthreads();
    }
    if (t < nb) part[t] = sm[t] - v;
    if (t == 1023) rowptr[n] = sm[1023];
}

__global__ void scanC(const int* __restrict__ deg, int n, const int* __restrict__ part,
                      int* __restrict__ rowptr, int* __restrict__ wptr) {
    __shared__ int sm[SCAN_CHUNK];
    int t = threadIdx.x;
    int gid = blockIdx.x * SCAN_CHUNK + t;
    int v = (gid < n) ? deg[gid] : 0;
    sm[t] = v;
    __syncthreads();
    for (int off = 1; off < SCAN_CHUNK; off <<= 1) {
        int add = (t >= off) ? sm[t - off] : 0;
        __syncthreads();
        sm[t] += add;
        __syncthreads();
    }
    if (gid < n) {
        int r = part[blockIdx.x] + sm[t] - v;
        rowptr[gid] = r;
        wptr[gid] = r;
    }
}

__global__ void scatter_csr(const int* __restrict__ ei, int E,
                            int* __restrict__ wptr, int* __restrict__ csrc) {
    int e = blockIdx.x * blockDim.x + threadIdx.x;
    if (e >= E) return;
    int d = ei[E + e];
    int pos = atomicAdd(&wptr[d], 1);
    csrc[pos] = ei[e];
}

// ---------------- fold attention vectors into ws ----------------
// ws[o*IN_DIM+k] = sum_c W[k][hd*16+c]*a[hd*16+c];  o<4: a_src head o, o>=4: a_dst
template <int IN_DIM>
__global__ void prep_ws(const float* __restrict__ W, const float* __restrict__ a_src,
                        const float* __restrict__ a_dst, float* __restrict__ ws) {
    int idx = blockIdx.x * blockDim.x + threadIdx.x;
    if (idx >= 8 * IN_DIM) return;
    int o = idx / IN_DIM, k = idx % IN_DIM;
    const float* a = (o < 4) ? a_src : a_dst;
    int hd = o & 3;
    float acc = 0.0f;
#pragma unroll
    for (int c = 0; c < 16; c++)
        acc = fmaf(W[k * 64 + hd * 16 + c], a[hd * 16 + c], acc);
    ws[idx] = acc;
}

// ---------------- staging helpers ----------------
template <int TEMP, int IN_DIM>
__device__ __forceinline__ void stage_cp(float* sbuf, const float* __restrict__ in,
                                         const float* __restrict__ tf,
                                         const float* __restrict__ Wt,
                                         const float* __restrict__ bt,
                                         int g0, int n, int tid) {
    if (TEMP) {
        // 56 real cols as 14 float4 via cp.async
        for (int i = tid; i < 32 * 14; i += 256) {
            int nl = i / 14, c4 = i - nl * 14;
            int node = g0 + nl;
            if (node < n)
                cp16(&sbuf[nl * 72 + c4 * 4], &in[(long)node * 56 + c4 * 4]);
        }
        // temporal 16 cols computed directly (plain STS)
        for (int i = tid; i < 32 * 4; i += 256) {
            int nl = i >> 2, q = i & 3;
            int node = g0 + nl;
            if (node < n) {
                float tv = tf[node];
                float4 r;
                r.x = fmaxf(fmaf(tv, Wt[q * 4 + 0], bt[q * 4 + 0]), 0.0f);
                r.y = fmaxf(fmaf(tv, Wt[q * 4 + 1], bt[q * 4 + 1]), 0.0f);
                r.z = fmaxf(fmaf(tv, Wt[q * 4 + 2], bt[q * 4 + 2]), 0.0f);
                r.w = fmaxf(fmaf(tv, Wt[q * 4 + 3], bt[q * 4 + 3]), 0.0f);
                *(float4*)&sbuf[nl * 72 + 56 + q * 4] = r;
            }
        }
    } else {
        for (int i = tid; i < 32 * 16; i += 256) {
            int nl = i >> 4, c4 = i & 15;
            int node = g0 + nl;
            if (node < n)
                cp16(&sbuf[nl * 64 + c4 * 4], &in[(long)node * 64 + c4 * 4]);
        }
    }
}

// ---------------- linear layer (h only), cp.async double-buffered ----------------
// 256 threads = 64 cols x 4 groups; each group 8 nodes per iter (32 nodes/iter).
// W column lives in registers for the whole kernel.
template <int TEMP, int IN_DIM>
__global__ void __launch_bounds__(256, 2)
lin_h(const float* __restrict__ in,
      const float* __restrict__ tf, const float* __restrict__ Wt,
      const float* __restrict__ bt,
      const float* __restrict__ W,
      float* __restrict__ h_out, int n) {
    __shared__ float sx[2][32 * IN_DIM];
    int tid = threadIdx.x;
    int group = tid >> 6;
    int j = tid & 63;

    float wreg[IN_DIM];
#pragma unroll
    for (int k = 0; k < IN_DIM; k++) wreg[k] = W[k * 64 + j];

    int stride = gridDim.x * 32;
    int g0 = blockIdx.x * 32;
    if (g0 >= n) return;

    stage_cp<TEMP, IN_DIM>(sx[0], in, tf, Wt, bt, g0, n, tid);
    cp_commit();
    int buf = 0;

    for (; g0 < n; g0 += stride) {
        int gn = g0 + stride;
        bool have_next = gn < n;
        if (have_next) {
            stage_cp<TEMP, IN_DIM>(sx[buf ^ 1], in, tf, Wt, bt, gn, n, tid);
            cp_commit();
            cp_wait<1>();
        } else {
            cp_wait<0>();
        }
        __syncthreads();

        float acc[8];
#pragma unroll
        for (int r = 0; r < 8; r++) acc[r] = 0.0f;
        const float* xbase = &sx[buf][(group * 8) * IN_DIM];
#pragma unroll
        for (int rh = 0; rh < 2; rh++) {
#pragma unroll
            for (int k = 0; k < IN_DIM; k += 4) {
                float4 xv[4];
#pragma unroll
                for (int r = 0; r < 4; r++)
                    xv[r] = *(const float4*)&xbase[(rh * 4 + r) * IN_DIM + k];
#pragma unroll
                for (int r = 0; r < 4; r++) {
                    acc[rh * 4 + r] = fmaf(wreg[k + 0], xv[r].x, acc[rh * 4 + r]);
                    acc[rh * 4 + r] = fmaf(wreg[k + 1], xv[r].y, acc[rh * 4 + r]);
                    acc[rh * 4 + r] = fmaf(wreg[k + 2], xv[r].z, acc[rh * 4 + r]);
                    acc[rh * 4 + r] = fmaf(wreg[k + 3], xv[r].w, acc[rh * 4 + r]);
                }
            }
        }
#pragma unroll
        for (int r = 0; r < 8; r++) {
            int node = g0 + group * 8 + r;
            if (node < n) h_out[(long)node * 64 + j] = acc[r];
        }
        __syncthreads();
        buf ^= 1;
    }
}

// ---------------- attention logits directly from x via folded ws ----------------
// 256 threads = 32 nodes x 8 outputs (4 src heads + 4 dst heads).
template <int TEMP, int IN_DIM>
__global__ void att_sd(const float* __restrict__ in,
                       const float* __restrict__ tf, const float* __restrict__ Wt,
                       const float* __restrict__ bt,
                       const float* __restrict__ ws,
                       float* __restrict__ s_out, float* __restrict__ d_out_, int n) {
    __shared__ float sx[32 * IN_DIM];
    __shared__ float sws[8 * IN_DIM];
    int tid = threadIdx.x;
    for (int i = tid; i < 8 * IN_DIM; i += 256) sws[i] = ws[i];

    int g0 = blockIdx.x * 32;
    if (TEMP) {
        for (int i = tid; i < 32 * 14; i += 256) {
            int nl = i / 14, c4 = i - nl * 14;
            int node = g0 + nl;
            if (node < n)
                *(float4*)&sx[nl * 72 + c4 * 4] =
                    *(const float4*)&in[(long)node * 56 + c4 * 4];
        }
        for (int i = tid; i < 32 * 4; i += 256) {
            int nl = i >> 2, q = i & 3;
            int node = g0 + nl;
            if (node < n) {
                float tv = tf[node];
                float4 r;
                r.x = fmaxf(fmaf(tv, Wt[q * 4 + 0], bt[q * 4 + 0]), 0.0f);
                r.y = fmaxf(fmaf(tv, Wt[q * 4 + 1], bt[q * 4 + 1]), 0.0f);
                r.z = fmaxf(fmaf(tv, Wt[q * 4 + 2], bt[q * 4 + 2]), 0.0f);
                r.w = fmaxf(fmaf(tv, Wt[q * 4 + 3], bt[q * 4 + 3]), 0.0f);
                *(float4*)&sx[nl * 72 + 56 + q * 4] = r;
            }
        }
    } else {
        for (int i = tid; i < 32 * 16; i += 256) {
            int nl = i >> 4, c4 = i & 15;
            int node = g0 + nl;
            if (node < n)
                *(float4*)&sx[nl * 64 + c4 * 4] =
                    *(const float4*)&in[(long)node * 64 + c4 * 4];
        }
    }
    __syncthreads();

    int nl = tid >> 3, o = tid & 7;
    int node = g0 + nl;
    if (node >= n) return;
    const float* xr = &sx[nl * IN_DIM];
    const float* wr = &sws[o * IN_DIM];
    float acc = 0.0f;
#pragma unroll
    for (int k = 0; k < IN_DIM; k += 4) {
        float4 xv = *(const float4*)&xr[k];
        float4 wv = *(const float4*)&wr[k];
        acc = fmaf(xv.x, wv.x, acc);
        acc = fmaf(xv.y, wv.y, acc);
        acc = fmaf(xv.z, wv.z, acc);
        acc = fmaf(xv.w, wv.w, acc);
    }
    if (o < 4) s_out[node * 4 + o] = acc;
    else       d_out_[node * 4 + o - 4] = acc;
}

// ---------------- fused GAT aggregation + softmax-normalize + LN + ReLU ----------------
__global__ void gat_agg(const int* __restrict__ rowptr, const int* __restrict__ csrc,
                        const float* __restrict__ s_, const float* __restrict__ d_,
                        const float* __restrict__ h_,
                        const float* __restrict__ b,
                        const float* __restrict__ gma, const float* __restrict__ bta,
                        float* __restrict__ out, int n) {
    int lane = threadIdx.x & 31;
    int sub  = lane >> 4;
    int l    = lane & 15;
    int node = blockIdx.x * (blockDim.x >> 5) + (threadIdx.x >> 5);
    if (node >= n) return;
    int head = l >> 2;
    float dlog = d_[node * 4 + head];

    float4 acc = make_float4(0.f, 0.f, 0.f, 0.f);
    float z = 0.0f;
    if (sub == 0) {   // self-loop
        float w = __expf(lrelu(s_[node * 4 + head] + dlog));
        z = w;
        float4 hv = *(const float4*)&h_[(long)node * 64 + l * 4];
        acc = make_float4(w * hv.x, w * hv.y, w * hv.z, w * hv.w);
    }

    int beg = rowptr[node], end = rowptr[node + 1];
    int i = beg + sub;
    for (; i + 6 < end; i += 8) {
        int s0 = csrc[i];
        int s1 = csrc[i + 2];
        int s2 = csrc[i + 4];
        int s3 = csrc[i + 6];
        float e0 = s_[s0 * 4 + head];
        float e1 = s_[s1 * 4 + head];
        float e2 = s_[s2 * 4 + head];
        float e3 = s_[s3 * 4 + head];
        float4 h0 = *(const float4*)&h_[(long)s0 * 64 + l * 4];
        float4 h1 = *(const float4*)&h_[(long)s1 * 64 + l * 4];
        float4 h2 = *(const float4*)&h_[(long)s2 * 64 + l * 4];
        float4 h3 = *(const float4*)&h_[(long)s3 * 64 + l * 4];
        float w0 = __expf(lrelu(e0 + dlog));
        float w1 = __expf(lrelu(e1 + dlog));
        float w2 = __expf(lrelu(e2 + dlog));
        float w3 = __expf(lrelu(e3 + dlog));
        z += (w0 + w1) + (w2 + w3);
        acc.x = fmaf(w0, h0.x, acc.x); acc.x = fmaf(w1, h1.x, acc.x);
        acc.x = fmaf(w2, h2.x, acc.x); acc.x = fmaf(w3, h3.x, acc.x);
        acc.y = fmaf(w0, h0.y, acc.y); acc.y = fmaf(w1, h1.y, acc.y);
        acc.y = fmaf(w2, h2.y, acc.y); acc.y = fmaf(w3, h3.y, acc.y);
        acc.z = fmaf(w0, h0.z, acc.z); acc.z = fmaf(w1, h1.z, acc.z);
        acc.z = fmaf(w2, h2.z, acc.z); acc.z = fmaf(w3, h3.z, acc.z);
        acc.w = fmaf(w0, h0.w, acc.w); acc.w = fmaf(w1, h1.w, acc.w);
        acc.w = fmaf(w2, h2.w, acc.w); acc.w = fmaf(w3, h3.w, acc.w);
    }
    for (; i < end; i += 2) {
        int s0 = csrc[i];
        float w0 = __expf(lrelu(s_[s0 * 4 + head] + dlog));
        float4 h0 = *(const float4*)&h_[(long)s0 * 64 + l * 4];
        z += w0;
        acc.x = fmaf(w0, h0.x, acc.x);
        acc.y = fmaf(w0, h0.y, acc.y);
        acc.z = fmaf(w0, h0.z, acc.z);
        acc.w = fmaf(w0, h0.w, acc.w);
    }

    z     += __shfl_xor_sync(0xffffffffu, z, 16);
    acc.x += __shfl_xor_sync(0xffffffffu, acc.x, 16);
    acc.y += __shfl_xor_sync(0xffffffffu, acc.y, 16);
    acc.z += __shfl_xor_sync(0xffffffffu, acc.z, 16);
    acc.w += __shfl_xor_sync(0xffffffffu, acc.w, 16);

    float zinv = 1.0f / (z + 1e-16f);
    float4 v;
    v.x = acc.x * zinv + b[l * 4 + 0];
    v.y = acc.y * zinv + b[l * 4 + 1];
    v.z = acc.z * zinv + b[l * 4 + 2];
    v.w = acc.w * zinv + b[l * 4 + 3];

    float sum = v.x + v.y + v.z + v.w;
    float sq  = v.x * v.x + v.y * v.y + v.z * v.z + v.w * v.w;
#pragma unroll
    for (int off = 8; off; off >>= 1) {
        sum += __shfl_xor_sync(0xffffffffu, sum, off, 16);
        sq  += __shfl_xor_sync(0xffffffffu, sq, off, 16);
    }
    float mean = sum * (1.0f / 64.0f);
    float var  = sq * (1.0f / 64.0f) - mean * mean;
    float inv  = rsqrtf(var + LN_EPS);
    float4 o;
    o.x = (v.x - mean) * inv * gma[l * 4 + 0] + bta[l * 4 + 0];
    o.y = (v.y - mean) * inv * gma[l * 4 + 1] + bta[l * 4 + 1];
    o.z = (v.z - mean) * inv * gma[l * 4 + 2] + bta[l * 4 + 2];
    o.w = (v.w - mean) * inv * gma[l * 4 + 3] + bta[l * 4 + 3];
    o.x = o.x > 0.0f ? o.x : 0.0f;
    o.y = o.y > 0.0f ? o.y : 0.0f;
    o.z = o.z > 0.0f ? o.z : 0.0f;
    o.w = o.w > 0.0f ? o.w : 0.0f;
    if (sub == 0)
        *(float4*)&out[(long)node * 64 + l * 4] = o;
}

// ---------------- global mean (column sums) ----------------
__global__ void colsum(const float* __restrict__ x2, int n, float* __restrict__ acc) {
    int col = threadIdx.x & 63;
    int rowgrp = threadIdx.x >> 6;
    float s = 0.0f;
    for (int r = blockIdx.x * 4 + rowgrp; r < n; r += gridDim.x * 4)
        s += x2[(long)r * 64 + col];
    __shared__ float sm[256];
    sm[threadIdx.x] = s;
    __syncthreads();
    if (threadIdx.x < 64) {
        float t = sm[threadIdx.x] + sm[threadIdx.x + 64] +
                  sm[threadIdx.x + 128] + sm[threadIdx.x + 192];
        atomicAdd(&acc[threadIdx.x], t);
    }
}

// ---------------- final MLP on mean-pooled embedding ----------------
__global__ void final_mlp(const float* __restrict__ acc, int n,
                          const float* __restrict__ Wp1, const float* __restrict__ bp1,
                          const float* __restrict__ Wp2, const float* __restrict__ bp2,
                          float* __restrict__ out) {
    __shared__ float gein[64], hid[64];
    int t = threadIdx.x;
    gein[t] = acc[t] / (float)n;
    __syncthreads();
    float a = bp1[t];
#pragma unroll
    for (int k = 0; k < 64; k++) a = fmaf(gein[k], Wp1[k * 64 + t], a);
    hid[t] = a > 0.0f ? a : 0.0f;
    __syncthreads();
    float o = bp2[t];
#pragma unroll
    for (int k = 0; k < 64; k++) o = fmaf(hid[k], Wp2[k * 64 + t], o);
    out[t] = o;
}

// ---------------- host launch ----------------
extern "C" void kernel_launch(void* const* d_in, const int* in_sizes, int n_in,
                              void* d_out, int out_size) {
    const float* x   = (const float*)d_in[0];
    const float* tf  = (const float*)d_in[1];
    const int*   ei  = (const int*)d_in[2];
    const float* Wt  = (const float*)d_in[3];
    const float* bt  = (const float*)d_in[4];
    const float* W1  = (const float*)d_in[5];
    const float* as1 = (const float*)d_in[6];
    const float* ad1 = (const float*)d_in[7];
    const float* b1  = (const float*)d_in[8];
    const float* g1  = (const float*)d_in[9];
    const float* be1 = (const float*)d_in[10];
    const float* W2  = (const float*)d_in[11];
    const float* as2 = (const float*)d_in[12];
    const float* ad2 = (const float*)d_in[13];
    const float* b2  = (const float*)d_in[14];
    const float* g2  = (const float*)d_in[15];
    const float* be2 = (const float*)d_in[16];
    const float* Wp1 = (const float*)d_in[17];
    const float* bp1 = (const float*)d_in[18];
    const float* Wp2 = (const float*)d_in[19];
    const float* bp2 = (const float*)d_in[20];

    int n = in_sizes[0] / 56;
    int E = in_sizes[2] / 2;

    float* out = (float*)d_out;
    float* x2  = out;
    float* ge  = out + (long)n * 64;

    float *h, *x1, *s, *d, *gacc, *ws;
    int *deg, *rowptr, *wptr, *csrc, *part;
    cudaGetSymbolAddress((void**)&h,      g_h);
    cudaGetSymbolAddress((void**)&x1,     g_x1);
    cudaGetSymbolAddress((void**)&s,      g_s);
    cudaGetSymbolAddress((void**)&d,      g_d);
    cudaGetSymbolAddress((void**)&gacc,   g_gacc);
    cudaGetSymbolAddress((void**)&ws,     g_ws);
    cudaGetSymbolAddress((void**)&deg,    g_deg);
    cudaGetSymbolAddress((void**)&rowptr, g_rowptr);
    cudaGetSymbolAddress((void**)&wptr,   g_wptr);
    cudaGetSymbolAddress((void**)&csrc,   g_csrc);
    cudaGetSymbolAddress((void**)&part,   g_part);

    const int TB = 256;
    int ebk = (E + TB - 1) / TB;
    int nwb = (n + 7) / 8;
    int nsb = (n + SCAN_CHUNK - 1) / SCAN_CHUNK;
    int sdb = (n + 31) / 32;       // att_sd blocks
    const int LGB = 296;           // 2 blocks per SM, persistent style

    // ---- CSR build (launch #4 = lin_h<1> for profiling) ----
    filli<<<(n + TB - 1) / TB, TB>>>(deg, 0, n);                    // 1
    hist_deg<<<ebk, TB>>>(ei, E, deg);                              // 2
    scanA<<<nsb, SCAN_CHUNK>>>(deg, n, part);                       // 3
    lin_h<1, 72><<<LGB, TB>>>(x, tf, Wt, bt, W1, h, n);             // 4 (profiled)
    scanB<<<1, 1024>>>(part, nsb, n, rowptr);                       // 5
    scanC<<<nsb, SCAN_CHUNK>>>(deg, n, part, rowptr, wptr);         // 6
    scatter_csr<<<ebk, TB>>>(ei, E, wptr, csrc);                    // 7

    // ---- layer 1 attention logits + aggregation ----
    prep_ws<72><<<3, TB>>>(W1, as1, ad1, ws);
    att_sd<1, 72><<<sdb, TB>>>(x, tf, Wt, bt, ws, s, d, n);
    gat_agg<<<nwb, TB>>>(rowptr, csrc, s, d, h, b1, g1, be1, x1, n);

    // ---- layer 2 ----
    lin_h<0, 64><<<LGB, TB>>>(x1, tf, Wt, bt, W2, h, n);
    prep_ws<64><<<2, TB>>>(W2, as2, ad2, ws);
    att_sd<0, 64><<<sdb, TB>>>(x1, tf, Wt, bt, ws, s, d, n);
    gat_agg<<<nwb, TB>>>(rowptr, csrc, s, d, h, b2, g2, be2, x2, n);

    // ---- global mean pool + MLP ----
    fillf<<<1, 64>>>(gacc, 0.0f, 64);
    colsum<<<1024, TB>>>(x2, n, gacc);
    final_mlp<<<1, 64>>>(gacc, n, Wp1, bp1, Wp2, bp2, ge);
}

// round 8
// speedup vs baseline: 2.1138x; 1.1518x over previous
#include <cuda_runtime.h>
#include <math.h>

#define NMAX 100000
#define EMAX 1600000
#define NEG_SLOPE 0.2f
#define LN_EPS 1e-5f
#define SCAN_CHUNK 512

// ---------------- scratch (device globals; no allocation) ----------------
__device__ __align__(16) float g_h[NMAX * 64];   // per-layer linear output
__device__ __align__(16) float g_x1[NMAX * 64];  // layer-1 output
__device__ __align__(16) float g_s[NMAX * 4];    // layer-1 src logits
__device__ __align__(16) float g_d[NMAX * 4];    // layer-1 dst logits
__device__ __align__(16) float g_s2[NMAX * 4];   // layer-2 src logits
__device__ __align__(16) float g_d2[NMAX * 4];   // layer-2 dst logits
__device__ __align__(16) float g_ws[8 * 72];     // folded attn weights (layer 1)
__device__ __align__(16) float g_ws2[8 * 64];    // folded attn weights (layer 2)
__device__ int   g_deg[NMAX];
__device__ int   g_rowptr[NMAX + 1];
__device__ int   g_wptr[NMAX];
__device__ int   g_csrc[EMAX];
__device__ int   g_part[1024];
__device__ float g_gacc[64];

__device__ __forceinline__ float lrelu(float v) {
    return v > 0.0f ? v : NEG_SLOPE * v;
}

// ---------------- cp.async helpers ----------------
__device__ __forceinline__ unsigned smem_u32(const void* p) {
    return (unsigned)__cvta_generic_to_shared(p);
}
__device__ __forceinline__ void cp16(void* dst, const void* src) {
    asm volatile("cp.async.cg.shared.global [%0], [%1], 16;"
                 :: "r"(smem_u32(dst)), "l"(src));
}
__device__ __forceinline__ void cp_commit() {
    asm volatile("cp.async.commit_group;" ::: "memory");
}
template <int N>
__device__ __forceinline__ void cp_wait() {
    asm volatile("cp.async.wait_group %0;" :: "n"(N) : "memory");
}

// ---------------- small fills ----------------
__global__ void fillf(float* p, float v, int n) {
    int i = blockIdx.x * blockDim.x + threadIdx.x;
    if (i < n) p[i] = v;
}
__global__ void filli(int* p, int v, int n) {
    int i = blockIdx.x * blockDim.x + threadIdx.x;
    if (i < n) p[i] = v;
}

// ---------------- CSR build ----------------
__global__ void hist_deg(const int* __restrict__ ei, int E, int* __restrict__ deg) {
    int e = blockIdx.x * blockDim.x + threadIdx.x;
    if (e < E) atomicAdd(&deg[ei[E + e]], 1);
}

__global__ void scanA(const int* __restrict__ deg, int n, int* __restrict__ part) {
    __shared__ int sm[SCAN_CHUNK];
    int gid = blockIdx.x * SCAN_CHUNK + threadIdx.x;
    sm[threadIdx.x] = (gid < n) ? deg[gid] : 0;
    __syncthreads();
    for (int off = SCAN_CHUNK / 2; off > 0; off >>= 1) {
        if (threadIdx.x < off) sm[threadIdx.x] += sm[threadIdx.x + off];
        __syncthreads();
    }
    if (threadIdx.x == 0) part[blockIdx.x] = sm[0];
}

__global__ void scanB(int* __restrict__ part, int nb, int n, int* __restrict__ rowptr) {
    __shared__ int sm[1024];
    int t = threadIdx.x;
    int v = (t < nb) ? part[t] : 0;
    sm[t] = v;
    __syncthreads();
    for (int off = 1; off < 1024; off <<= 1) {
        int add = (t >= off) ? sm[t - off] : 0;
        __syncthreads();
        sm[t] += add;
        __syncthreads();
    }
    if (t < nb) part[t] = sm[t] - v;
    if (t == 1023) rowptr[n] = sm[1023];
}

__global__ void scanC(const int* __restrict__ deg, int n, const int* __restrict__ part,
                      int* __restrict__ rowptr, int* __restrict__ wptr) {
    __shared__ int sm[SCAN_CHUNK];
    int t = threadIdx.x;
    int gid = blockIdx.x * SCAN_CHUNK + t;
    int v = (gid < n) ? deg[gid] : 0;
    sm[t] = v;
    __syncthreads();
    for (int off = 1; off < SCAN_CHUNK; off <<= 1) {
        int add = (t >= off) ? sm[t - off] : 0;
        __syncthreads();
        sm[t] += add;
        __syncthreads();
    }
    if (gid < n) {
        int r = part[blockIdx.x] + sm[t] - v;
        rowptr[gid] = r;
        wptr[gid] = r;
    }
}

__global__ void scatter_csr(const int* __restrict__ ei, int E,
                            int* __restrict__ wptr, int* __restrict__ csrc) {
    int e = blockIdx.x * blockDim.x + threadIdx.x;
    if (e >= E) return;
    int d = ei[E + e];
    int pos = atomicAdd(&wptr[d], 1);
    csrc[pos] = ei[e];
}

// ---------------- fold attention vectors into ws ----------------
template <int IN_DIM>
__global__ void prep_ws(const float* __restrict__ W, const float* __restrict__ a_src,
                        const float* __restrict__ a_dst, float* __restrict__ ws) {
    int idx = blockIdx.x * blockDim.x + threadIdx.x;
    if (idx >= 8 * IN_DIM) return;
    int o = idx / IN_DIM, k = idx % IN_DIM;
    const float* a = (o < 4) ? a_src : a_dst;
    int hd = o & 3;
    float acc = 0.0f;
#pragma unroll
    for (int c = 0; c < 16; c++)
        acc = fmaf(W[k * 64 + hd * 16 + c], a[hd * 16 + c], acc);
    ws[idx] = acc;
}

// ---------------- staging helper ----------------
template <int TEMP, int IN_DIM>
__device__ __forceinline__ void stage_cp(float* sbuf, const float* __restrict__ in,
                                         const float* __restrict__ tf,
                                         const float* __restrict__ Wt,
                                         const float* __restrict__ bt,
                                         int g0, int n, int tid) {
    if (TEMP) {
        for (int i = tid; i < 32 * 14; i += 256) {
            int nl = i / 14, c4 = i - nl * 14;
            int node = g0 + nl;
            if (node < n)
                cp16(&sbuf[nl * 72 + c4 * 4], &in[(long)node * 56 + c4 * 4]);
        }
        for (int i = tid; i < 32 * 4; i += 256) {
            int nl = i >> 2, q = i & 3;
            int node = g0 + nl;
            if (node < n) {
                float tv = tf[node];
                float4 r;
                r.x = fmaxf(fmaf(tv, Wt[q * 4 + 0], bt[q * 4 + 0]), 0.0f);
                r.y = fmaxf(fmaf(tv, Wt[q * 4 + 1], bt[q * 4 + 1]), 0.0f);
                r.z = fmaxf(fmaf(tv, Wt[q * 4 + 2], bt[q * 4 + 2]), 0.0f);
                r.w = fmaxf(fmaf(tv, Wt[q * 4 + 3], bt[q * 4 + 3]), 0.0f);
                *(float4*)&sbuf[nl * 72 + 56 + q * 4] = r;
            }
        }
    } else {
        for (int i = tid; i < 32 * 16; i += 256) {
            int nl = i >> 4, c4 = i & 15;
            int node = g0 + nl;
            if (node < n)
                cp16(&sbuf[nl * 64 + c4 * 4], &in[(long)node * 64 + c4 * 4]);
        }
    }
}

// ---------------- linear layer (h [+ fused s/d logits]) ----------------
// 256 threads = 64 cols x 4 groups, 8 nodes per group (32 nodes/iter),
// cp.async double-buffered; W column in registers.
// EPI=1: also computes s/d = x . ws from the staged tile (layer 1).
template <int TEMP, int IN_DIM, int EPI>
__global__ void __launch_bounds__(256, 2)
lin_h(const float* __restrict__ in,
      const float* __restrict__ tf, const float* __restrict__ Wt,
      const float* __restrict__ bt,
      const float* __restrict__ W, const float* __restrict__ ws,
      float* __restrict__ h_out,
      float* __restrict__ s_out, float* __restrict__ d_out_, int n) {
    __shared__ float sx[2][32 * IN_DIM];
    __shared__ float sws[EPI ? 8 * IN_DIM : 8];
    int tid = threadIdx.x;
    int group = tid >> 6;
    int j = tid & 63;

    if (EPI) {
        for (int i = tid; i < 8 * IN_DIM; i += 256) sws[i] = ws[i];
    }

    float wreg[IN_DIM];
#pragma unroll
    for (int k = 0; k < IN_DIM; k++) wreg[k] = W[k * 64 + j];

    int stride = gridDim.x * 32;
    int g0 = blockIdx.x * 32;
    if (g0 >= n) return;

    stage_cp<TEMP, IN_DIM>(sx[0], in, tf, Wt, bt, g0, n, tid);
    cp_commit();
    int buf = 0;

    for (; g0 < n; g0 += stride) {
        int gn = g0 + stride;
        bool have_next = gn < n;
        if (have_next) {
            stage_cp<TEMP, IN_DIM>(sx[buf ^ 1], in, tf, Wt, bt, gn, n, tid);
            cp_commit();
            cp_wait<1>();
        } else {
            cp_wait<0>();
        }
        __syncthreads();

        float acc[8];
#pragma unroll
        for (int r = 0; r < 8; r++) acc[r] = 0.0f;
        const float* xbase = &sx[buf][(group * 8) * IN_DIM];
#pragma unroll
        for (int rh = 0; rh < 2; rh++) {
#pragma unroll
            for (int k = 0; k < IN_DIM; k += 4) {
                float4 xv[4];
#pragma unroll
                for (int r = 0; r < 4; r++)
                    xv[r] = *(const float4*)&xbase[(rh * 4 + r) * IN_DIM + k];
#pragma unroll
                for (int r = 0; r < 4; r++) {
                    acc[rh * 4 + r] = fmaf(wreg[k + 0], xv[r].x, acc[rh * 4 + r]);
                    acc[rh * 4 + r] = fmaf(wreg[k + 1], xv[r].y, acc[rh * 4 + r]);
                    acc[rh * 4 + r] = fmaf(wreg[k + 2], xv[r].z, acc[rh * 4 + r]);
                    acc[rh * 4 + r] = fmaf(wreg[k + 3], xv[r].w, acc[rh * 4 + r]);
                }
            }
        }
#pragma unroll
        for (int r = 0; r < 8; r++) {
            int node = g0 + group * 8 + r;
            if (node < n) h_out[(long)node * 64 + j] = acc[r];
        }

        if (EPI) {
            // s/d epilogue: 256 threads = 32 nodes x 8 outputs, tile still valid
            int nl = tid >> 3, o = tid & 7;
            int node = g0 + nl;
            if (node < n) {
                const float* xr = &sx[buf][nl * IN_DIM];
                const float* wr = &sws[o * IN_DIM];
                float a2 = 0.0f;
#pragma unroll
                for (int k = 0; k < IN_DIM; k += 4) {
                    float4 xv = *(const float4*)&xr[k];
                    float4 wv = *(const float4*)&wr[k];
                    a2 = fmaf(xv.x, wv.x, a2);
                    a2 = fmaf(xv.y, wv.y, a2);
                    a2 = fmaf(xv.z, wv.z, a2);
                    a2 = fmaf(xv.w, wv.w, a2);
                }
                if (o < 4) s_out[node * 4 + o] = a2;
                else       d_out_[node * 4 + o - 4] = a2;
            }
        }
        __syncthreads();
        buf ^= 1;
    }
}

// ---------------- fused GAT aggregation + softmax-norm + LN + ReLU ----------------
// Full warp per dst node, two 16-lane sub-halves, x4 unroll.
// EPI=1: additionally computes next layer's s2/d2 = out . ws2 in registers.
template <int EPI>
__global__ void gat_agg(const int* __restrict__ rowptr, const int* __restrict__ csrc,
                        const float* __restrict__ s_, const float* __restrict__ d_,
                        const float* __restrict__ h_,
                        const float* __restrict__ b,
                        const float* __restrict__ gma, const float* __restrict__ bta,
                        const float* __restrict__ ws2,
                        float* __restrict__ s2_out, float* __restrict__ d2_out,
                        float* __restrict__ out, int n) {
    int lane = threadIdx.x & 31;
    int sub  = lane >> 4;
    int l    = lane & 15;
    int node = blockIdx.x * (blockDim.x >> 5) + (threadIdx.x >> 5);
    if (node >= n) return;
    int head = l >> 2;
    float dlog = d_[node * 4 + head];

    float4 acc = make_float4(0.f, 0.f, 0.f, 0.f);
    float z = 0.0f;
    if (sub == 0) {   // self-loop
        float w = __expf(lrelu(s_[node * 4 + head] + dlog));
        z = w;
        float4 hv = *(const float4*)&h_[(long)node * 64 + l * 4];
        acc = make_float4(w * hv.x, w * hv.y, w * hv.z, w * hv.w);
    }

    int beg = rowptr[node], end = rowptr[node + 1];
    int i = beg + sub;
    for (; i + 6 < end; i += 8) {
        int s0 = csrc[i];
        int s1 = csrc[i + 2];
        int s2 = csrc[i + 4];
        int s3 = csrc[i + 6];
        float e0 = s_[s0 * 4 + head];
        float e1 = s_[s1 * 4 + head];
        float e2 = s_[s2 * 4 + head];
        float e3 = s_[s3 * 4 + head];
        float4 h0 = *(const float4*)&h_[(long)s0 * 64 + l * 4];
        float4 h1 = *(const float4*)&h_[(long)s1 * 64 + l * 4];
        float4 h2 = *(const float4*)&h_[(long)s2 * 64 + l * 4];
        float4 h3 = *(const float4*)&h_[(long)s3 * 64 + l * 4];
        float w0 = __expf(lrelu(e0 + dlog));
        float w1 = __expf(lrelu(e1 + dlog));
        float w2 = __expf(lrelu(e2 + dlog));
        float w3 = __expf(lrelu(e3 + dlog));
        z += (w0 + w1) + (w2 + w3);
        acc.x = fmaf(w0, h0.x, acc.x); acc.x = fmaf(w1, h1.x, acc.x);
        acc.x = fmaf(w2, h2.x, acc.x); acc.x = fmaf(w3, h3.x, acc.x);
        acc.y = fmaf(w0, h0.y, acc.y); acc.y = fmaf(w1, h1.y, acc.y);
        acc.y = fmaf(w2, h2.y, acc.y); acc.y = fmaf(w3, h3.y, acc.y);
        acc.z = fmaf(w0, h0.z, acc.z); acc.z = fmaf(w1, h1.z, acc.z);
        acc.z = fmaf(w2, h2.z, acc.z); acc.z = fmaf(w3, h3.z, acc.z);
        acc.w = fmaf(w0, h0.w, acc.w); acc.w = fmaf(w1, h1.w, acc.w);
        acc.w = fmaf(w2, h2.w, acc.w); acc.w = fmaf(w3, h3.w, acc.w);
    }
    for (; i < end; i += 2) {
        int s0 = csrc[i];
        float w0 = __expf(lrelu(s_[s0 * 4 + head] + dlog));
        float4 h0 = *(const float4*)&h_[(long)s0 * 64 + l * 4];
        z += w0;
        acc.x = fmaf(w0, h0.x, acc.x);
        acc.y = fmaf(w0, h0.y, acc.y);
        acc.z = fmaf(w0, h0.z, acc.z);
        acc.w = fmaf(w0, h0.w, acc.w);
    }

    z     += __shfl_xor_sync(0xffffffffu, z, 16);
    acc.x += __shfl_xor_sync(0xffffffffu, acc.x, 16);
    acc.y += __shfl_xor_sync(0xffffffffu, acc.y, 16);
    acc.z += __shfl_xor_sync(0xffffffffu, acc.z, 16);
    acc.w += __shfl_xor_sync(0xffffffffu, acc.w, 16);

    float zinv = 1.0f / (z + 1e-16f);
    float4 v;
    v.x = acc.x * zinv + b[l * 4 + 0];
    v.y = acc.y * zinv + b[l * 4 + 1];
    v.z = acc.z * zinv + b[l * 4 + 2];
    v.w = acc.w * zinv + b[l * 4 + 3];

    float sum = v.x + v.y + v.z + v.w;
    float sq  = v.x * v.x + v.y * v.y + v.z * v.z + v.w * v.w;
#pragma unroll
    for (int off = 8; off; off >>= 1) {
        sum += __shfl_xor_sync(0xffffffffu, sum, off, 16);
        sq  += __shfl_xor_sync(0xffffffffu, sq, off, 16);
    }
    float mean = sum * (1.0f / 64.0f);
    float var  = sq * (1.0f / 64.0f) - mean * mean;
    float inv  = rsqrtf(var + LN_EPS);
    float4 o;
    o.x = (v.x - mean) * inv * gma[l * 4 + 0] + bta[l * 4 + 0];
    o.y = (v.y - mean) * inv * gma[l * 4 + 1] + bta[l * 4 + 1];
    o.z = (v.z - mean) * inv * gma[l * 4 + 2] + bta[l * 4 + 2];
    o.w = (v.w - mean) * inv * gma[l * 4 + 3] + bta[l * 4 + 3];
    o.x = o.x > 0.0f ? o.x : 0.0f;
    o.y = o.y > 0.0f ? o.y : 0.0f;
    o.z = o.z > 0.0f ? o.z : 0.0f;
    o.w = o.w > 0.0f ? o.w : 0.0f;
    if (sub == 0)
        *(float4*)&out[(long)node * 64 + l * 4] = o;

    if (EPI) {
        // next-layer logits: s2/d2[node][hd] = sum_k out[node][k]*ws2[o][k]
        float p[8];
#pragma unroll
        for (int q = 0; q < 8; q++) {
            float4 wv = *(const float4*)&ws2[q * 64 + l * 4];
            p[q] = v.x > 0.0f || true ? 0.0f : 0.0f;  // init
            p[q] = fmaf(o.x, wv.x, 0.0f);
            p[q] = fmaf(o.y, wv.y, p[q]);
            p[q] = fmaf(o.z, wv.z, p[q]);
            p[q] = fmaf(o.w, wv.w, p[q]);
        }
#pragma unroll
        for (int q = 0; q < 8; q++) {
#pragma unroll
            for (int off = 8; off; off >>= 1)
                p[q] += __shfl_xor_sync(0xffffffffu, p[q], off, 16);
        }
        if (sub == 0 && l == 0) {
            *(float4*)&s2_out[node * 4] = make_float4(p[0], p[1], p[2], p[3]);
            *(float4*)&d2_out[node * 4] = make_float4(p[4], p[5], p[6], p[7]);
        }
    }
}

// ---------------- global mean (column sums) ----------------
__global__ void colsum(const float* __restrict__ x2, int n, float* __restrict__ acc) {
    int col = threadIdx.x & 63;
    int rowgrp = threadIdx.x >> 6;
    float s = 0.0f;
    for (int r = blockIdx.x * 4 + rowgrp; r < n; r += gridDim.x * 4)
        s += x2[(long)r * 64 + col];
    __shared__ float sm[256];
    sm[threadIdx.x] = s;
    __syncthreads();
    if (threadIdx.x < 64) {
        float t = sm[threadIdx.x] + sm[threadIdx.x + 64] +
                  sm[threadIdx.x + 128] + sm[threadIdx.x + 192];
        atomicAdd(&acc[threadIdx.x], t);
    }
}

// ---------------- final MLP on mean-pooled embedding ----------------
__global__ void final_mlp(const float* __restrict__ acc, int n,
                          const float* __restrict__ Wp1, const float* __restrict__ bp1,
                          const float* __restrict__ Wp2, const float* __restrict__ bp2,
                          float* __restrict__ out) {
    __shared__ float gein[64], hid[64];
    int t = threadIdx.x;
    gein[t] = acc[t] / (float)n;
    __syncthreads();
    float a = bp1[t];
#pragma unroll
    for (int k = 0; k < 64; k++) a = fmaf(gein[k], Wp1[k * 64 + t], a);
    hid[t] = a > 0.0f ? a : 0.0f;
    __syncthreads();
    float o = bp2[t];
#pragma unroll
    for (int k = 0; k < 64; k++) o = fmaf(hid[k], Wp2[k * 64 + t], o);
    out[t] = o;
}

// ---------------- host launch ----------------
extern "C" void kernel_launch(void* const* d_in, const int* in_sizes, int n_in,
                              void* d_out, int out_size) {
    const float* x   = (const float*)d_in[0];
    const float* tf  = (const float*)d_in[1];
    const int*   ei  = (const int*)d_in[2];
    const float* Wt  = (const float*)d_in[3];
    const float* bt  = (const float*)d_in[4];
    const float* W1  = (const float*)d_in[5];
    const float* as1 = (const float*)d_in[6];
    const float* ad1 = (const float*)d_in[7];
    const float* b1  = (const float*)d_in[8];
    const float* g1  = (const float*)d_in[9];
    const float* be1 = (const float*)d_in[10];
    const float* W2  = (const float*)d_in[11];
    const float* as2 = (const float*)d_in[12];
    const float* ad2 = (const float*)d_in[13];
    const float* b2  = (const float*)d_in[14];
    const float* g2  = (const float*)d_in[15];
    const float* be2 = (const float*)d_in[16];
    const float* Wp1 = (const float*)d_in[17];
    const float* bp1 = (const float*)d_in[18];
    const float* Wp2 = (const float*)d_in[19];
    const float* bp2 = (const float*)d_in[20];

    int n = in_sizes[0] / 56;
    int E = in_sizes[2] / 2;

    float* out = (float*)d_out;
    float* x2  = out;
    float* ge  = out + (long)n * 64;

    float *h, *x1, *s, *d, *s2, *d2, *gacc, *ws, *ws2;
    int *deg, *rowptr, *wptr, *csrc, *part;
    cudaGetSymbolAddress((void**)&h,      g_h);
    cudaGetSymbolAddress((void**)&x1,     g_x1);
    cudaGetSymbolAddress((void**)&s,      g_s);
    cudaGetSymbolAddress((void**)&d,      g_d);
    cudaGetSymbolAddress((void**)&s2,     g_s2);
    cudaGetSymbolAddress((void**)&d2,     g_d2);
    cudaGetSymbolAddress((void**)&gacc,   g_gacc);
    cudaGetSymbolAddress((void**)&ws,     g_ws);
    cudaGetSymbolAddress((void**)&ws2,    g_ws2);
    cudaGetSymbolAddress((void**)&deg,    g_deg);
    cudaGetSymbolAddress((void**)&rowptr, g_rowptr);
    cudaGetSymbolAddress((void**)&wptr,   g_wptr);
    cudaGetSymbolAddress((void**)&csrc,   g_csrc);
    cudaGetSymbolAddress((void**)&part,   g_part);

    const int TB = 256;
    int ebk = (E + TB - 1) / TB;
    int nwb = (n + 7) / 8;
    int nsb = (n + SCAN_CHUNK - 1) / SCAN_CHUNK;
    const int LGB = 296;

    // 1-3: prep + CSR start
    prep_ws<72><<<3, TB>>>(W1, as1, ad1, ws);
    filli<<<(n + TB - 1) / TB, TB>>>(deg, 0, n);
    hist_deg<<<ebk, TB>>>(ei, E, deg);
    // 4: profiled — layer-1 linear + fused s/d
    lin_h<1, 72, 1><<<LGB, TB>>>(x, tf, Wt, bt, W1, ws, h, s, d, n);
    // 5-8: finish CSR
    scanA<<<nsb, SCAN_CHUNK>>>(deg, n, part);
    scanB<<<1, 1024>>>(part, nsb, n, rowptr);
    scanC<<<nsb, SCAN_CHUNK>>>(deg, n, part, rowptr, wptr);
    scatter_csr<<<ebk, TB>>>(ei, E, wptr, csrc);
    // 9: fold layer-2 attention weights (needed by gat_agg L1 epilogue)
    prep_ws<64><<<2, TB>>>(W2, as2, ad2, ws2);
    // 10: layer-1 aggregation + fused layer-2 logits
    gat_agg<1><<<nwb, TB>>>(rowptr, csrc, s, d, h, b1, g1, be1, ws2, s2, d2, x1, n);
    // 11: layer-2 linear (no epilogue)
    lin_h<0, 64, 0><<<LGB, TB>>>(x1, tf, Wt, bt, W2, ws2, h, s2, d2, n);
    // 12: layer-2 aggregation
    gat_agg<0><<<nwb, TB>>>(rowptr, csrc, s2, d2, h, b2, g2, be2, ws2, s2, d2, x2, n);
    // 13-15: pool + MLP
    fillf<<<1, 64>>>(gacc, 0.0f, 64);
    colsum<<<1024, TB>>>(x2, n, gacc);
    final_mlp<<<1, 64>>>(gacc, n, Wp1, bp1, Wp2, bp2, ge);
}